// round 3
// baseline (speedup 1.0000x reference)
#include <cuda_runtime.h>

// ---------------------------------------------------------------------------
// Problem constants (fixed shapes from reference_code)
// ---------------------------------------------------------------------------
#define BATCH 2
#define SEQ   2048
#define CDIM  1024
#define NHEAD 16
#define HDIM  64
#define MROWS (BATCH * SEQ)     // 4096
#define QKVN  (3 * CDIM)        // 3072

// Flash-attention tiling
#define BQ    64
#define BKEY  64
#define LDSS  68                // padded smem row length (64 + 4), float4-aligned
#define SMEM_FLOATS (4 * 64 * LDSS + 3 * 64)
#define SMEM_BYTES  (SMEM_FLOATS * 4)

// Scratch (allocation-free: __device__ globals)
__device__ float g_qkv[MROWS * QKVN];   // 50.3 MB
__device__ float g_y[MROWS * CDIM];     // 16.8 MB

// ---------------------------------------------------------------------------
// SGEMM + bias: C[M,N] = A[M,K] @ B[K,N] + bias[N]
// 128x128 block tile, BK=8, 8x8 per-thread micro-tile, 256 threads.
// M,N multiples of 128; K multiple of 8. All row-major fp32.
// ---------------------------------------------------------------------------
__global__ __launch_bounds__(256)
void sgemm_bias(const float* __restrict__ A, const float* __restrict__ B,
                const float* __restrict__ bias, float* __restrict__ Cout,
                int M, int N, int K)
{
    constexpr int BM = 128, BN = 128, BK = 8, TM = 8, TN = 8;
    __shared__ float As[BK][BM];   // stored transposed: As[k][m]
    __shared__ float Bs[BK][BN];

    const int tid = threadIdx.x;
    const int bx = blockIdx.x, by = blockIdx.y;
    const int tr = tid >> 4;       // 0..15 (row group)
    const int tc = tid & 15;       // 0..15 (col group)
    const int aRow = tid >> 1;     // 0..127
    const int aCol = tid & 1;      // float4 slot in k
    const int bRow = tid >> 5;     // 0..7
    const int bCol = tid & 31;     // float4 slot in n

    const float* Ap = A + (size_t)by * BM * K;
    const float* Bp = B + (size_t)bx * BN;

    float acc[TM][TN];
    #pragma unroll
    for (int i = 0; i < TM; i++)
        #pragma unroll
        for (int j = 0; j < TN; j++) acc[i][j] = 0.0f;

    for (int k0 = 0; k0 < K; k0 += BK) {
        // Load A tile (128x8), store transposed
        float4 a4 = *reinterpret_cast<const float4*>(Ap + (size_t)aRow * K + k0 + aCol * 4);
        As[aCol * 4 + 0][aRow] = a4.x;
        As[aCol * 4 + 1][aRow] = a4.y;
        As[aCol * 4 + 2][aRow] = a4.z;
        As[aCol * 4 + 3][aRow] = a4.w;
        // Load B tile (8x128)
        float4 b4 = *reinterpret_cast<const float4*>(Bp + (size_t)(k0 + bRow) * N + bCol * 4);
        *reinterpret_cast<float4*>(&Bs[bRow][bCol * 4]) = b4;
        __syncthreads();

        #pragma unroll
        for (int k = 0; k < BK; k++) {
            float rm[TM], rn[TN];
            #pragma unroll
            for (int i = 0; i < TM; i++) rm[i] = As[k][tr * TM + i];
            #pragma unroll
            for (int j = 0; j < TN; j++) rn[j] = Bs[k][tc * TN + j];
            #pragma unroll
            for (int i = 0; i < TM; i++)
                #pragma unroll
                for (int j = 0; j < TN; j++)
                    acc[i][j] = fmaf(rm[i], rn[j], acc[i][j]);
        }
        __syncthreads();
    }

    // Epilogue: + bias, vectorized store
    #pragma unroll
    for (int i = 0; i < TM; i++) {
        const int row = by * BM + tr * TM + i;
        #pragma unroll
        for (int j = 0; j < TN; j += 4) {
            const int col = bx * BN + tc * TN + j;
            float4 o;
            o.x = acc[i][j + 0] + __ldg(&bias[col + 0]);
            o.y = acc[i][j + 1] + __ldg(&bias[col + 1]);
            o.z = acc[i][j + 2] + __ldg(&bias[col + 2]);
            o.w = acc[i][j + 3] + __ldg(&bias[col + 3]);
            *reinterpret_cast<float4*>(Cout + (size_t)row * N + col) = o;
        }
    }
}

// ---------------------------------------------------------------------------
// Flash attention (fp32, causal + padding mask, online softmax).
// Block = (q_tile, head, batch). 256 threads as a 16x16 grid; 4x4 micro-tiles
// for both S = Q K^T and O += P V phases. Q,K stored d-major ([d][m]) in smem
// for float4 reads; P stored [key][m]; V natural [key][d].
// Reads g_qkv (q at col h*64, k at C + h*64, v at 2C + h*64), writes g_y.
// ---------------------------------------------------------------------------
__global__ __launch_bounds__(256)
void flash_attn(const int* __restrict__ mask)
{
    extern __shared__ float sm[];
    float* Qs   = sm;                    // [HDIM][LDSS]  (d-major)
    float* Ks   = Qs + HDIM * LDSS;      // [HDIM][LDSS]  (d-major)
    float* Vs   = Ks + HDIM * LDSS;      // [BKEY][LDSS]  (key-major)
    float* Ps   = Vs + BKEY * LDSS;      // [BKEY][LDSS]  scores/probs, [key][m]
    float* mrow = Ps + BKEY * LDSS;      // [BQ] running max
    float* lrow = mrow + BQ;             // [BQ] running sum
    float* arow = lrow + BQ;             // [BQ] rescale factor

    const int qt = blockIdx.x, h = blockIdx.y, b = blockIdx.z;
    const int tid = threadIdx.x;
    const int ty = tid >> 4, tx = tid & 15;
    const int q0 = qt * BQ;

    const float* qbase = g_qkv + (size_t)b * SEQ * QKVN + h * HDIM;
    const float* kbase = qbase + CDIM;
    const float* vbase = qbase + 2 * CDIM;
    const int* mb = mask + b * SEQ;

    // Load Q tile, transpose into [d][m]
    for (int idx = tid; idx < BQ * (HDIM / 4); idx += 256) {
        const int m = idx >> 4;
        const int dc = idx & 15;
        float4 q4 = *reinterpret_cast<const float4*>(qbase + (size_t)(q0 + m) * QKVN + dc * 4);
        Qs[(dc * 4 + 0) * LDSS + m] = q4.x;
        Qs[(dc * 4 + 1) * LDSS + m] = q4.y;
        Qs[(dc * 4 + 2) * LDSS + m] = q4.z;
        Qs[(dc * 4 + 3) * LDSS + m] = q4.w;
    }
    if (tid < BQ) { mrow[tid] = -1e30f; lrow[tid] = 0.0f; }

    float Oacc[4][4];
    #pragma unroll
    for (int i = 0; i < 4; i++)
        #pragma unroll
        for (int j = 0; j < 4; j++) Oacc[i][j] = 0.0f;

    __syncthreads();

    for (int kt = 0; kt <= qt; kt++) {
        const int k0 = kt * BKEY;

        // Load K (transposed to [d][n]) and V (natural [n][d])
        for (int idx = tid; idx < BKEY * (HDIM / 4); idx += 256) {
            const int n = idx >> 4;
            const int dc = idx & 15;
            float4 k4 = *reinterpret_cast<const float4*>(kbase + (size_t)(k0 + n) * QKVN + dc * 4);
            Ks[(dc * 4 + 0) * LDSS + n] = k4.x;
            Ks[(dc * 4 + 1) * LDSS + n] = k4.y;
            Ks[(dc * 4 + 2) * LDSS + n] = k4.z;
            Ks[(dc * 4 + 3) * LDSS + n] = k4.w;
            float4 v4 = *reinterpret_cast<const float4*>(vbase + (size_t)(k0 + n) * QKVN + dc * 4);
            *reinterpret_cast<float4*>(&Vs[n * LDSS + dc * 4]) = v4;
        }
        __syncthreads();

        // Phase A: S[i][j] = sum_d Q[q0+ty*4+i][d] * K[k0+tx*4+j][d]
        float sacc[4][4];
        #pragma unroll
        for (int i = 0; i < 4; i++)
            #pragma unroll
            for (int j = 0; j < 4; j++) sacc[i][j] = 0.0f;

        #pragma unroll 8
        for (int d = 0; d < HDIM; d++) {
            float4 qa = *reinterpret_cast<const float4*>(&Qs[d * LDSS + ty * 4]);
            float4 ka = *reinterpret_cast<const float4*>(&Ks[d * LDSS + tx * 4]);
            const float qv[4] = {qa.x, qa.y, qa.z, qa.w};
            const float kv[4] = {ka.x, ka.y, ka.z, ka.w};
            #pragma unroll
            for (int i = 0; i < 4; i++)
                #pragma unroll
                for (int j = 0; j < 4; j++)
                    sacc[i][j] = fmaf(qv[i], kv[j], sacc[i][j]);
        }

        // Scale + causal/pad mask; write S transposed into Ps[key][m]
        #pragma unroll
        for (int j = 0; j < 4; j++) {
            const int gk = k0 + tx * 4 + j;
            const bool kvalid = (__ldg(&mb[gk]) != 0);
            #pragma unroll
            for (int i = 0; i < 4; i++) {
                const int gq = q0 + ty * 4 + i;
                float s = sacc[i][j] * 0.125f;   // 1/sqrt(64)
                if (gk > gq || !kvalid) s = -1e30f;
                Ps[(tx * 4 + j) * LDSS + (ty * 4 + i)] = s;
            }
        }
        __syncthreads();

        // Online softmax: 4 threads per row (quad = consecutive lanes)
        {
            const int r = tid >> 2, part = tid & 3;
            float mx = -1e30f;
            #pragma unroll
            for (int n = part * 16; n < part * 16 + 16; n++)
                mx = fmaxf(mx, Ps[n * LDSS + r]);
            mx = fmaxf(mx, __shfl_xor_sync(0xffffffffu, mx, 1));
            mx = fmaxf(mx, __shfl_xor_sync(0xffffffffu, mx, 2));
            const float mold = mrow[r];
            const float mnew = fmaxf(mold, mx);
            float sum = 0.0f;
            #pragma unroll
            for (int n = part * 16; n < part * 16 + 16; n++) {
                const float p = __expf(Ps[n * LDSS + r] - mnew);
                Ps[n * LDSS + r] = p;
                sum += p;
            }
            sum += __shfl_xor_sync(0xffffffffu, sum, 1);
            sum += __shfl_xor_sync(0xffffffffu, sum, 2);
            if (part == 0) {
                const float al = __expf(mold - mnew);
                mrow[r] = mnew;
                lrow[r] = lrow[r] * al + sum;
                arow[r] = al;
            }
        }
        __syncthreads();

        // Phase C: O[i][j] = O[i][j]*alpha[row] + sum_n P[n][row] * V[n][col]
        float al[4];
        #pragma unroll
        for (int i = 0; i < 4; i++) al[i] = arow[ty * 4 + i];
        #pragma unroll
        for (int i = 0; i < 4; i++)
            #pragma unroll
            for (int j = 0; j < 4; j++) Oacc[i][j] *= al[i];

        #pragma unroll 8
        for (int n = 0; n < BKEY; n++) {
            float4 pa = *reinterpret_cast<const float4*>(&Ps[n * LDSS + ty * 4]);
            float4 va = *reinterpret_cast<const float4*>(&Vs[n * LDSS + tx * 4]);
            const float pv[4] = {pa.x, pa.y, pa.z, pa.w};
            const float vv[4] = {va.x, va.y, va.z, va.w};
            #pragma unroll
            for (int i = 0; i < 4; i++)
                #pragma unroll
                for (int j = 0; j < 4; j++)
                    Oacc[i][j] = fmaf(pv[i], vv[j], Oacc[i][j]);
        }
        __syncthreads();   // before next tile overwrites Ks/Vs/Ps
    }

    // Epilogue: normalize and write y[b, q, h*64 + d]
    #pragma unroll
    for (int i = 0; i < 4; i++) {
        const float inv = 1.0f / lrow[ty * 4 + i];
        float4 o;
        o.x = Oacc[i][0] * inv;
        o.y = Oacc[i][1] * inv;
        o.z = Oacc[i][2] * inv;
        o.w = Oacc[i][3] * inv;
        *reinterpret_cast<float4*>(
            g_y + (size_t)(b * SEQ + q0 + ty * 4 + i) * CDIM + h * HDIM + tx * 4) = o;
    }
}

// ---------------------------------------------------------------------------
// Launch: qkv = x@Wqkv+b ; flash attention ; out = y@Wproj+b
// ---------------------------------------------------------------------------
extern "C" void kernel_launch(void* const* d_in, const int* in_sizes, int n_in,
                              void* d_out, int out_size)
{
    const float* x     = (const float*)d_in[0];
    const int*   mask  = (const int*)  d_in[1];
    const float* Wqkv  = (const float*)d_in[2];
    const float* bqkv  = (const float*)d_in[3];
    const float* Wproj = (const float*)d_in[4];
    const float* bproj = (const float*)d_in[5];
    float* out = (float*)d_out;

    float *qkv_ptr = nullptr, *y_ptr = nullptr;
    cudaGetSymbolAddress((void**)&qkv_ptr, g_qkv);
    cudaGetSymbolAddress((void**)&y_ptr, g_y);

    cudaFuncSetAttribute(flash_attn,
                         cudaFuncAttributeMaxDynamicSharedMemorySize, SMEM_BYTES);

    // 1) QKV GEMM: [4096,1024] @ [1024,3072] + bias
    dim3 g1(QKVN / 128, MROWS / 128);
    sgemm_bias<<<g1, 256>>>(x, Wqkv, bqkv, qkv_ptr, MROWS, QKVN, CDIM);

    // 2) Flash attention: grid = (q_tiles, heads, batch)
    dim3 g2(SEQ / BQ, NHEAD, BATCH);
    flash_attn<<<g2, 256, SMEM_BYTES>>>(mask);

    // 3) Projection GEMM: [4096,1024] @ [1024,1024] + bias -> out
    dim3 g3(CDIM / 128, MROWS / 128);
    sgemm_bias<<<g3, 256>>>(y_ptr, Wproj, bproj, out, MROWS, CDIM, CDIM);
}

// round 7
// speedup vs baseline: 1.5123x; 1.5123x over previous
#include <cuda_runtime.h>
#include <cuda_bf16.h>
#include <cstdint>

// ---------------------------------------------------------------------------
// Problem constants
// ---------------------------------------------------------------------------
#define BATCH 2
#define SEQ   2048
#define CDIM  1024
#define NHEAD 16
#define HDIM  64
#define MROWS (BATCH * SEQ)     // 4096
#define QKVN  (3 * CDIM)        // 3072

// Flash-attention tiling
#define BQ    64
#define BKEY  64
#define LDSS  68
#define SMEM_FLOATS (4 * 64 * LDSS + 3 * 64)
#define SMEM_BYTES  (SMEM_FLOATS * 4)

// GEMM tiling (warp-level mma.sync path; tcgen05 unavailable: harness compiles
// through compute_103 PTX which rejects tcgen05.*)
// GPITCH MUST be a multiple of 16 (ldmatrix requires 16B-aligned row addrs);
// 80B = 5*16B is also bank-conflict-free: rows 0..7 start at banks
// {0,20,8,28,16,4,24,12} and their 16B reads tile all 32 banks exactly once.
#define GBM 128
#define GBN 128
#define GBK 32
#define GPITCH 80                      // smem row pitch bytes (64B data + 16B pad)
#define GTILE  (128 * GPITCH)          // 10240 B per tile
#define GSTAGE (4 * GTILE)             // Ah,Al,Bh,Bl = 40960 B
#define GSMEM  (2 * GSTAGE)            // double buffered = 81920 B
#define NKT    (CDIM / GBK)            // 32 k-tiles

// ---------------------------------------------------------------------------
// Scratch (allocation-free __device__ globals)
// ---------------------------------------------------------------------------
__device__ float g_qkv[MROWS * QKVN];                 // 50.3 MB fp32
__device__ float g_y[MROWS * CDIM];                   // 16.8 MB fp32
__device__ __align__(16) __nv_bfloat16 g_xh[MROWS * CDIM];
__device__ __align__(16) __nv_bfloat16 g_xl[MROWS * CDIM];
__device__ __align__(16) __nv_bfloat16 g_yh[MROWS * CDIM];
__device__ __align__(16) __nv_bfloat16 g_yl[MROWS * CDIM];
__device__ __align__(16) __nv_bfloat16 g_wqh[QKVN * CDIM];   // W^T [3072][1024]
__device__ __align__(16) __nv_bfloat16 g_wql[QKVN * CDIM];
__device__ __align__(16) __nv_bfloat16 g_wph[CDIM * CDIM];   // W^T [1024][1024]
__device__ __align__(16) __nv_bfloat16 g_wpl[CDIM * CDIM];

// ---------------------------------------------------------------------------
// PTX helpers (sm_80-era: valid on compute_103)
// ---------------------------------------------------------------------------
__device__ __forceinline__ uint32_t smem_u32(const void* p) {
    uint32_t a;
    asm("{ .reg .u64 t; cvta.to.shared.u64 t, %1; cvt.u32.u64 %0, t; }"
        : "=r"(a) : "l"(p));
    return a;
}
__device__ __forceinline__ void cp_async16(uint32_t dst, const void* src) {
    asm volatile("cp.async.cg.shared.global [%0], [%1], 16;"
                 :: "r"(dst), "l"(src) : "memory");
}
__device__ __forceinline__ void cp_commit() {
    asm volatile("cp.async.commit_group;" ::: "memory");
}
__device__ __forceinline__ void cp_wait1() {
    asm volatile("cp.async.wait_group 1;" ::: "memory");
}
__device__ __forceinline__ void cp_wait0() {
    asm volatile("cp.async.wait_group 0;" ::: "memory");
}
__device__ __forceinline__ void ldm4(uint32_t* r, uint32_t addr) {
    asm volatile("ldmatrix.sync.aligned.m8n8.x4.shared.b16 {%0,%1,%2,%3}, [%4];"
                 : "=r"(r[0]), "=r"(r[1]), "=r"(r[2]), "=r"(r[3]) : "r"(addr));
}
__device__ __forceinline__ void mma_bf16(float* c, const uint32_t* a,
                                         uint32_t b0, uint32_t b1) {
    asm volatile(
        "mma.sync.aligned.m16n8k16.row.col.f32.bf16.bf16.f32 "
        "{%0,%1,%2,%3}, {%4,%5,%6,%7}, {%8,%9}, {%0,%1,%2,%3};"
        : "+f"(c[0]), "+f"(c[1]), "+f"(c[2]), "+f"(c[3])
        : "r"(a[0]), "r"(a[1]), "r"(a[2]), "r"(a[3]), "r"(b0), "r"(b1));
}

// ---------------------------------------------------------------------------
// fp32 -> bf16 split helpers / conversion kernels
// ---------------------------------------------------------------------------
__device__ __forceinline__ void split_bf16(float a, __nv_bfloat16& h, __nv_bfloat16& l) {
    h = __float2bfloat16(a);
    l = __float2bfloat16(a - __bfloat162float(h));
}

__global__ __launch_bounds__(256)
void split4(const float* __restrict__ in, __nv_bfloat16* __restrict__ hi,
            __nv_bfloat16* __restrict__ lo, int n4)
{
    int i = blockIdx.x * blockDim.x + threadIdx.x;
    if (i >= n4) return;
    float4 v = reinterpret_cast<const float4*>(in)[i];
    __nv_bfloat16 h0, h1, h2, h3, l0, l1, l2, l3;
    split_bf16(v.x, h0, l0); split_bf16(v.y, h1, l1);
    split_bf16(v.z, h2, l2); split_bf16(v.w, h3, l3);
    reinterpret_cast<__nv_bfloat162*>(hi)[2 * i]     = __halves2bfloat162(h0, h1);
    reinterpret_cast<__nv_bfloat162*>(hi)[2 * i + 1] = __halves2bfloat162(h2, h3);
    reinterpret_cast<__nv_bfloat162*>(lo)[2 * i]     = __halves2bfloat162(l0, l1);
    reinterpret_cast<__nv_bfloat162*>(lo)[2 * i + 1] = __halves2bfloat162(l2, l3);
}

// Transpose + split: W[1024][Ncols] fp32 -> T_hi/lo [Ncols][1024] bf16
__global__ __launch_bounds__(256)
void transpose_split(const float* __restrict__ W, __nv_bfloat16* __restrict__ Th,
                     __nv_bfloat16* __restrict__ Tl, int Ncols)
{
    __shared__ float t[32][33];
    const int tx = threadIdx.x, ty = threadIdx.y;
    const int n = blockIdx.x * 32 + tx;
    const int k0 = blockIdx.y * 32;
    #pragma unroll
    for (int j = 0; j < 4; j++)
        t[ty + j * 8][tx] = W[(size_t)(k0 + ty + j * 8) * Ncols + n];
    __syncthreads();
    const int nr = blockIdx.x * 32;
    #pragma unroll
    for (int j = 0; j < 4; j++) {
        float a = t[tx][ty + j * 8];           // = W[k0+tx][nr+ty+j*8]
        __nv_bfloat16 h, l;
        split_bf16(a, h, l);
        size_t o = (size_t)(nr + ty + j * 8) * CDIM + k0 + tx;
        Th[o] = h; Tl[o] = l;
    }
}

// ---------------------------------------------------------------------------
// bf16 split GEMM via mma.sync: C[M,N] = (Ah+Al)[M,1024] @ (Bh+Bl)^T + bias
// A: [M][1024] row-major bf16 (hi/lo).  B: [N][1024] row-major bf16 (hi/lo).
// 128x128 CTA tile, BK=32, 8 warps (2x4) of 64x32 warp tiles, cp.async
// double buffering, ldmatrix fragments, 3 split-combination mma passes.
// ---------------------------------------------------------------------------
__global__ __launch_bounds__(256, 2)
void gemm_bf16s(const __nv_bfloat16* __restrict__ Ah, const __nv_bfloat16* __restrict__ Al,
                const __nv_bfloat16* __restrict__ Bh, const __nv_bfloat16* __restrict__ Bl,
                const float* __restrict__ bias, float* __restrict__ C, int N)
{
    extern __shared__ char sm[];
    const uint32_t sb = smem_u32(sm);
    const int tid = threadIdx.x;
    const int lane = tid & 31, warp = tid >> 5;
    const int wm = (warp >> 2) * 64;         // warp row offset in CTA tile
    const int wn = (warp & 3) * 32;          // warp col offset
    const int m0 = blockIdx.y * GBM, n0 = blockIdx.x * GBN;

    // Per-thread ldmatrix base offsets (within a split tile); all 16B-aligned
    // because GPITCH % 16 == 0.
    const uint32_t aoff = (uint32_t)((wm + (lane & 15)) * GPITCH + (lane >> 4) * 16);
    const uint32_t boff = (uint32_t)((wn + (lane & 7)) * GPITCH + ((lane >> 3) & 1) * 16
                                     + (lane >> 4) * (8 * GPITCH));

    float acc[4][4][4];
    #pragma unroll
    for (int i = 0; i < 4; i++)
        #pragma unroll
        for (int j = 0; j < 4; j++)
            #pragma unroll
            for (int q = 0; q < 4; q++) acc[i][j][q] = 0.0f;

    // ---- stage loader: 4 tiles x 128 rows x 64B (pitch 80B) ----
    auto issue = [&](int kt, int buf) {
        const int k0 = kt * GBK;
        const uint32_t stg = sb + buf * GSTAGE;
        #pragma unroll
        for (int l = 0; l < 8; l++) {
            const int t = l >> 1;                       // 0:Ah 1:Al 2:Bh 3:Bl
            const int idx = tid + (l & 1) * 256;        // 0..511
            const int r = idx >> 2, c = idx & 3;
            const __nv_bfloat16* base = (t == 0) ? Ah : (t == 1) ? Al
                                        : (t == 2) ? Bh : Bl;
            const int grow = ((t < 2) ? m0 : n0) + r;
            cp_async16(stg + t * GTILE + r * GPITCH + c * 16,
                       base + (size_t)grow * CDIM + k0 + c * 8);
        }
        cp_commit();
    };

    issue(0, 0);
    for (int kt = 0; kt < NKT; kt++) {
        if (kt + 1 < NKT) { issue(kt + 1, (kt + 1) & 1); cp_wait1(); }
        else              { cp_wait0(); }
        __syncthreads();

        const uint32_t stg = sb + (kt & 1) * GSTAGE;
        const uint32_t a_hi = stg + 0 * GTILE + aoff;
        const uint32_t a_lo = stg + 1 * GTILE + aoff;
        const uint32_t b_hi = stg + 2 * GTILE + boff;
        const uint32_t b_lo = stg + 3 * GTILE + boff;

        #pragma unroll
        for (int ks = 0; ks < 2; ks++) {
            uint32_t ah[4][4], al[4][4];
            #pragma unroll
            for (int mt = 0; mt < 4; mt++) {
                ldm4(ah[mt], a_hi + mt * (16 * GPITCH) + ks * 32);
                ldm4(al[mt], a_lo + mt * (16 * GPITCH) + ks * 32);
            }
            #pragma unroll
            for (int p = 0; p < 2; p++) {
                uint32_t bh[4], bl[4];
                ldm4(bh, b_hi + p * (16 * GPITCH) + ks * 32);
                ldm4(bl, b_lo + p * (16 * GPITCH) + ks * 32);
                #pragma unroll
                for (int mt = 0; mt < 4; mt++) {
                    #pragma unroll
                    for (int q = 0; q < 2; q++) {
                        float* c = acc[mt][2 * p + q];
                        mma_bf16(c, ah[mt], bh[2 * q], bh[2 * q + 1]);
                        mma_bf16(c, ah[mt], bl[2 * q], bl[2 * q + 1]);
                        mma_bf16(c, al[mt], bh[2 * q], bh[2 * q + 1]);
                    }
                }
            }
        }
        __syncthreads();
    }

    // Epilogue: acc layout per mma m16n8: d0,d1 = (row, col..col+1); d2,d3 = row+8
    const int erow = lane >> 2, ecol = (lane & 3) * 2;
    #pragma unroll
    for (int mt = 0; mt < 4; mt++) {
        #pragma unroll
        for (int nt = 0; nt < 4; nt++) {
            const int row = m0 + wm + mt * 16 + erow;
            const int col = n0 + wn + nt * 8 + ecol;
            const float2 bv = *reinterpret_cast<const float2*>(bias + col);
            float2 v0, v1;
            v0.x = acc[mt][nt][0] + bv.x;
            v0.y = acc[mt][nt][1] + bv.y;
            v1.x = acc[mt][nt][2] + bv.x;
            v1.y = acc[mt][nt][3] + bv.y;
            *reinterpret_cast<float2*>(C + (size_t)row * N + col) = v0;
            *reinterpret_cast<float2*>(C + (size_t)(row + 8) * N + col) = v1;
        }
    }
}

// ---------------------------------------------------------------------------
// Flash attention (unchanged from validated R3 baseline)
// ---------------------------------------------------------------------------
__global__ __launch_bounds__(256)
void flash_attn(const int* __restrict__ mask)
{
    extern __shared__ float smf[];
    float* Qs   = smf;
    float* Ks   = Qs + HDIM * LDSS;
    float* Vs   = Ks + HDIM * LDSS;
    float* Ps   = Vs + BKEY * LDSS;
    float* mrow = Ps + BKEY * LDSS;
    float* lrow = mrow + BQ;
    float* arow = lrow + BQ;

    const int qt = blockIdx.x, h = blockIdx.y, b = blockIdx.z;
    const int tid = threadIdx.x;
    const int ty = tid >> 4, tx = tid & 15;
    const int q0 = qt * BQ;

    const float* qbase = g_qkv + (size_t)b * SEQ * QKVN + h * HDIM;
    const float* kbase = qbase + CDIM;
    const float* vbase = qbase + 2 * CDIM;
    const int* mb = mask + b * SEQ;

    for (int idx = tid; idx < BQ * (HDIM / 4); idx += 256) {
        const int m = idx >> 4;
        const int dc = idx & 15;
        float4 q4 = *reinterpret_cast<const float4*>(qbase + (size_t)(q0 + m) * QKVN + dc * 4);
        Qs[(dc * 4 + 0) * LDSS + m] = q4.x;
        Qs[(dc * 4 + 1) * LDSS + m] = q4.y;
        Qs[(dc * 4 + 2) * LDSS + m] = q4.z;
        Qs[(dc * 4 + 3) * LDSS + m] = q4.w;
    }
    if (tid < BQ) { mrow[tid] = -1e30f; lrow[tid] = 0.0f; }

    float Oacc[4][4];
    #pragma unroll
    for (int i = 0; i < 4; i++)
        #pragma unroll
        for (int j = 0; j < 4; j++) Oacc[i][j] = 0.0f;

    __syncthreads();

    for (int kt = 0; kt <= qt; kt++) {
        const int k0 = kt * BKEY;

        for (int idx = tid; idx < BKEY * (HDIM / 4); idx += 256) {
            const int n = idx >> 4;
            const int dc = idx & 15;
            float4 k4 = *reinterpret_cast<const float4*>(kbase + (size_t)(k0 + n) * QKVN + dc * 4);
            Ks[(dc * 4 + 0) * LDSS + n] = k4.x;
            Ks[(dc * 4 + 1) * LDSS + n] = k4.y;
            Ks[(dc * 4 + 2) * LDSS + n] = k4.z;
            Ks[(dc * 4 + 3) * LDSS + n] = k4.w;
            float4 v4 = *reinterpret_cast<const float4*>(vbase + (size_t)(k0 + n) * QKVN + dc * 4);
            *reinterpret_cast<float4*>(&Vs[n * LDSS + dc * 4]) = v4;
        }
        __syncthreads();

        float sacc[4][4];
        #pragma unroll
        for (int i = 0; i < 4; i++)
            #pragma unroll
            for (int j = 0; j < 4; j++) sacc[i][j] = 0.0f;

        #pragma unroll 8
        for (int d = 0; d < HDIM; d++) {
            float4 qa = *reinterpret_cast<const float4*>(&Qs[d * LDSS + ty * 4]);
            float4 ka = *reinterpret_cast<const float4*>(&Ks[d * LDSS + tx * 4]);
            const float qv[4] = {qa.x, qa.y, qa.z, qa.w};
            const float kv[4] = {ka.x, ka.y, ka.z, ka.w};
            #pragma unroll
            for (int i = 0; i < 4; i++)
                #pragma unroll
                for (int j = 0; j < 4; j++)
                    sacc[i][j] = fmaf(qv[i], kv[j], sacc[i][j]);
        }

        #pragma unroll
        for (int j = 0; j < 4; j++) {
            const int gk = k0 + tx * 4 + j;
            const bool kvalid = (__ldg(&mb[gk]) != 0);
            #pragma unroll
            for (int i = 0; i < 4; i++) {
                const int gq = q0 + ty * 4 + i;
                float s = sacc[i][j] * 0.125f;
                if (gk > gq || !kvalid) s = -1e30f;
                Ps[(tx * 4 + j) * LDSS + (ty * 4 + i)] = s;
            }
        }
        __syncthreads();

        {
            const int r = tid >> 2, part = tid & 3;
            float mx = -1e30f;
            #pragma unroll
            for (int n = part * 16; n < part * 16 + 16; n++)
                mx = fmaxf(mx, Ps[n * LDSS + r]);
            mx = fmaxf(mx, __shfl_xor_sync(0xffffffffu, mx, 1));
            mx = fmaxf(mx, __shfl_xor_sync(0xffffffffu, mx, 2));
            const float mold = mrow[r];
            const float mnew = fmaxf(mold, mx);
            float sum = 0.0f;
            #pragma unroll
            for (int n = part * 16; n < part * 16 + 16; n++) {
                const float p = __expf(Ps[n * LDSS + r] - mnew);
                Ps[n * LDSS + r] = p;
                sum += p;
            }
            sum += __shfl_xor_sync(0xffffffffu, sum, 1);
            sum += __shfl_xor_sync(0xffffffffu, sum, 2);
            if (part == 0) {
                const float al = __expf(mold - mnew);
                mrow[r] = mnew;
                lrow[r] = lrow[r] * al + sum;
                arow[r] = al;
            }
        }
        __syncthreads();

        float al[4];
        #pragma unroll
        for (int i = 0; i < 4; i++) al[i] = arow[ty * 4 + i];
        #pragma unroll
        for (int i = 0; i < 4; i++)
            #pragma unroll
            for (int j = 0; j < 4; j++) Oacc[i][j] *= al[i];

        #pragma unroll 8
        for (int n = 0; n < BKEY; n++) {
            float4 pa = *reinterpret_cast<const float4*>(&Ps[n * LDSS + ty * 4]);
            float4 va = *reinterpret_cast<const float4*>(&Vs[n * LDSS + tx * 4]);
            const float pv[4] = {pa.x, pa.y, pa.z, pa.w};
            const float vv[4] = {va.x, va.y, va.z, va.w};
            #pragma unroll
            for (int i = 0; i < 4; i++)
                #pragma unroll
                for (int j = 0; j < 4; j++)
                    Oacc[i][j] = fmaf(pv[i], vv[j], Oacc[i][j]);
        }
        __syncthreads();
    }

    #pragma unroll
    for (int i = 0; i < 4; i++) {
        const float inv = 1.0f / lrow[ty * 4 + i];
        float4 o;
        o.x = Oacc[i][0] * inv;
        o.y = Oacc[i][1] * inv;
        o.z = Oacc[i][2] * inv;
        o.w = Oacc[i][3] * inv;
        *reinterpret_cast<float4*>(
            g_y + (size_t)(b * SEQ + q0 + ty * 4 + i) * CDIM + h * HDIM + tx * 4) = o;
    }
}

// ---------------------------------------------------------------------------
// Launch
// ---------------------------------------------------------------------------
extern "C" void kernel_launch(void* const* d_in, const int* in_sizes, int n_in,
                              void* d_out, int out_size)
{
    const float* x     = (const float*)d_in[0];
    const int*   mask  = (const int*)  d_in[1];
    const float* Wqkv  = (const float*)d_in[2];
    const float* bqkv  = (const float*)d_in[3];
    const float* Wproj = (const float*)d_in[4];
    const float* bproj = (const float*)d_in[5];
    float* out = (float*)d_out;

    float *qkv_ptr, *y_ptr;
    __nv_bfloat16 *xh, *xl, *yh, *yl, *wqh, *wql, *wph, *wpl;
    cudaGetSymbolAddress((void**)&qkv_ptr, g_qkv);
    cudaGetSymbolAddress((void**)&y_ptr, g_y);
    cudaGetSymbolAddress((void**)&xh, g_xh);
    cudaGetSymbolAddress((void**)&xl, g_xl);
    cudaGetSymbolAddress((void**)&yh, g_yh);
    cudaGetSymbolAddress((void**)&yl, g_yl);
    cudaGetSymbolAddress((void**)&wqh, g_wqh);
    cudaGetSymbolAddress((void**)&wql, g_wql);
    cudaGetSymbolAddress((void**)&wph, g_wph);
    cudaGetSymbolAddress((void**)&wpl, g_wpl);

    cudaFuncSetAttribute(flash_attn,
                         cudaFuncAttributeMaxDynamicSharedMemorySize, SMEM_BYTES);
    cudaFuncSetAttribute(gemm_bf16s,
                         cudaFuncAttributeMaxDynamicSharedMemorySize, GSMEM);

    // Conversions: x split; weights transpose+split
    split4<<<(MROWS * CDIM / 4 + 255) / 256, 256>>>(x, xh, xl, MROWS * CDIM / 4);
    transpose_split<<<dim3(QKVN / 32, CDIM / 32), dim3(32, 8)>>>(Wqkv, wqh, wql, QKVN);
    transpose_split<<<dim3(CDIM / 32, CDIM / 32), dim3(32, 8)>>>(Wproj, wph, wpl, CDIM);

    // 1) QKV GEMM (tensor cores via mma.sync)
    gemm_bf16s<<<dim3(QKVN / GBN, MROWS / GBM), 256, GSMEM>>>(
        xh, xl, wqh, wql, bqkv, qkv_ptr, QKVN);

    // 2) Flash attention
    flash_attn<<<dim3(SEQ / BQ, NHEAD, BATCH), 256, SMEM_BYTES>>>(mask);

    // 3) Split y, projection GEMM
    split4<<<(MROWS * CDIM / 4 + 255) / 256, 256>>>(y_ptr, yh, yl, MROWS * CDIM / 4);
    gemm_bf16s<<<dim3(CDIM / GBN, MROWS / GBM), 256, GSMEM>>>(
        yh, yl, wph, wpl, bproj, out, CDIM);
}

// round 8
// speedup vs baseline: 2.8984x; 1.9166x over previous
#include <cuda_runtime.h>
#include <cuda_bf16.h>
#include <cstdint>

// ---------------------------------------------------------------------------
// Problem constants
// ---------------------------------------------------------------------------
#define BATCH 2
#define SEQ   2048
#define CDIM  1024
#define NHEAD 16
#define HDIM  64
#define MROWS (BATCH * SEQ)     // 4096
#define QKVN  (3 * CDIM)        // 3072

// GEMM tiling (warp-level mma.sync path; tcgen05 rejected by compute_103 PTX)
#define GBM 128
#define GBN 128
#define GBK 32
#define GPITCH 80                      // 64B data + 16B pad; 16B-aligned rows
#define GTILE  (128 * GPITCH)
#define GSTAGE (4 * GTILE)
#define GSMEM  (2 * GSTAGE)            // 81920 B
#define NKT    (CDIM / GBK)

// Flash tiling: 128 q-rows x 64-key tiles, 8 warps x 16 rows
#define FBQ    128
#define FPITCH 144                     // 64 bf16 (128B) + 16B pad; bank stride 4/row
#define FQH 0
#define FQL (128 * FPITCH)
#define FKH (2 * 128 * FPITCH)
#define FKL (FKH + 64 * FPITCH)
#define FVH (FKL + 64 * FPITCH)
#define FVL (FVH + 64 * FPITCH)
#define FMASK (FVL + 64 * FPITCH)
#define FSMEM (FMASK + 64 * 4)         // 73984 B

// ---------------------------------------------------------------------------
// Scratch (allocation-free __device__ globals)
// ---------------------------------------------------------------------------
__device__ __align__(16) __nv_bfloat16 g_qkvh[MROWS * QKVN];  // 25.2 MB
__device__ __align__(16) __nv_bfloat16 g_qkvl[MROWS * QKVN];
__device__ __align__(16) __nv_bfloat16 g_xh[MROWS * CDIM];
__device__ __align__(16) __nv_bfloat16 g_xl[MROWS * CDIM];
__device__ __align__(16) __nv_bfloat16 g_yh[MROWS * CDIM];
__device__ __align__(16) __nv_bfloat16 g_yl[MROWS * CDIM];
__device__ __align__(16) __nv_bfloat16 g_wqh[QKVN * CDIM];    // W^T [3072][1024]
__device__ __align__(16) __nv_bfloat16 g_wql[QKVN * CDIM];
__device__ __align__(16) __nv_bfloat16 g_wph[CDIM * CDIM];    // W^T [1024][1024]
__device__ __align__(16) __nv_bfloat16 g_wpl[CDIM * CDIM];

// ---------------------------------------------------------------------------
// PTX helpers (sm_80-era: valid on compute_103)
// ---------------------------------------------------------------------------
__device__ __forceinline__ uint32_t smem_u32(const void* p) {
    uint32_t a;
    asm("{ .reg .u64 t; cvta.to.shared.u64 t, %1; cvt.u32.u64 %0, t; }"
        : "=r"(a) : "l"(p));
    return a;
}
__device__ __forceinline__ void cp_async16(uint32_t dst, const void* src) {
    asm volatile("cp.async.cg.shared.global [%0], [%1], 16;"
                 :: "r"(dst), "l"(src) : "memory");
}
__device__ __forceinline__ void cp_commit() {
    asm volatile("cp.async.commit_group;" ::: "memory");
}
__device__ __forceinline__ void cp_wait1() {
    asm volatile("cp.async.wait_group 1;" ::: "memory");
}
__device__ __forceinline__ void cp_wait0() {
    asm volatile("cp.async.wait_group 0;" ::: "memory");
}
__device__ __forceinline__ void ldm4(uint32_t* r, uint32_t addr) {
    asm volatile("ldmatrix.sync.aligned.m8n8.x4.shared.b16 {%0,%1,%2,%3}, [%4];"
                 : "=r"(r[0]), "=r"(r[1]), "=r"(r[2]), "=r"(r[3]) : "r"(addr));
}
__device__ __forceinline__ void ldm4t(uint32_t* r, uint32_t addr) {
    asm volatile("ldmatrix.sync.aligned.m8n8.x4.trans.shared.b16 {%0,%1,%2,%3}, [%4];"
                 : "=r"(r[0]), "=r"(r[1]), "=r"(r[2]), "=r"(r[3]) : "r"(addr));
}
__device__ __forceinline__ void mma_bf16(float* c, const uint32_t* a,
                                         uint32_t b0, uint32_t b1) {
    asm volatile(
        "mma.sync.aligned.m16n8k16.row.col.f32.bf16.bf16.f32 "
        "{%0,%1,%2,%3}, {%4,%5,%6,%7}, {%8,%9}, {%0,%1,%2,%3};"
        : "+f"(c[0]), "+f"(c[1]), "+f"(c[2]), "+f"(c[3])
        : "r"(a[0]), "r"(a[1]), "r"(a[2]), "r"(a[3]), "r"(b0), "r"(b1));
}

// ---------------------------------------------------------------------------
// fp32 -> bf16 split helpers / conversion kernels
// ---------------------------------------------------------------------------
__device__ __forceinline__ void split_bf16(float a, __nv_bfloat16& h, __nv_bfloat16& l) {
    h = __float2bfloat16(a);
    l = __float2bfloat16(a - __bfloat162float(h));
}
__device__ __forceinline__ void split_pack2(float x, float y, uint32_t& hi, uint32_t& lo) {
    __nv_bfloat16 hx, lx, hy, ly;
    split_bf16(x, hx, lx);
    split_bf16(y, hy, ly);
    __nv_bfloat162 h2 = __halves2bfloat162(hx, hy);
    __nv_bfloat162 l2 = __halves2bfloat162(lx, ly);
    hi = *reinterpret_cast<uint32_t*>(&h2);
    lo = *reinterpret_cast<uint32_t*>(&l2);
}

__global__ __launch_bounds__(256)
void split4(const float* __restrict__ in, __nv_bfloat16* __restrict__ hi,
            __nv_bfloat16* __restrict__ lo, int n4)
{
    int i = blockIdx.x * blockDim.x + threadIdx.x;
    if (i >= n4) return;
    float4 v = reinterpret_cast<const float4*>(in)[i];
    uint32_t h0, l0, h1, l1;
    split_pack2(v.x, v.y, h0, l0);
    split_pack2(v.z, v.w, h1, l1);
    reinterpret_cast<uint32_t*>(hi)[2 * i]     = h0;
    reinterpret_cast<uint32_t*>(hi)[2 * i + 1] = h1;
    reinterpret_cast<uint32_t*>(lo)[2 * i]     = l0;
    reinterpret_cast<uint32_t*>(lo)[2 * i + 1] = l1;
}

// Transpose + split: W[1024][Ncols] fp32 -> T_hi/lo [Ncols][1024] bf16
__global__ __launch_bounds__(256)
void transpose_split(const float* __restrict__ W, __nv_bfloat16* __restrict__ Th,
                     __nv_bfloat16* __restrict__ Tl, int Ncols)
{
    __shared__ float t[32][33];
    const int tx = threadIdx.x, ty = threadIdx.y;
    const int n = blockIdx.x * 32 + tx;
    const int k0 = blockIdx.y * 32;
    #pragma unroll
    for (int j = 0; j < 4; j++)
        t[ty + j * 8][tx] = W[(size_t)(k0 + ty + j * 8) * Ncols + n];
    __syncthreads();
    const int nr = blockIdx.x * 32;
    #pragma unroll
    for (int j = 0; j < 4; j++) {
        float a = t[tx][ty + j * 8];
        __nv_bfloat16 h, l;
        split_bf16(a, h, l);
        size_t o = (size_t)(nr + ty + j * 8) * CDIM + k0 + tx;
        Th[o] = h; Tl[o] = l;
    }
}

// ---------------------------------------------------------------------------
// bf16 split GEMM via mma.sync: C = (Ah+Al) @ (Bh+Bl)^T + bias
// SPLIT=0: write fp32 C.  SPLIT=1: write bf16 hi/lo split (Ch, Cl).
// ---------------------------------------------------------------------------
template<int SPLIT>
__global__ __launch_bounds__(256, 2)
void gemm_bf16s(const __nv_bfloat16* __restrict__ Ah, const __nv_bfloat16* __restrict__ Al,
                const __nv_bfloat16* __restrict__ Bh, const __nv_bfloat16* __restrict__ Bl,
                const float* __restrict__ bias, float* __restrict__ C,
                __nv_bfloat16* __restrict__ Ch, __nv_bfloat16* __restrict__ Cl, int N)
{
    extern __shared__ char sm[];
    const uint32_t sb = smem_u32(sm);
    const int tid = threadIdx.x;
    const int lane = tid & 31, warp = tid >> 5;
    const int wm = (warp >> 2) * 64;
    const int wn = (warp & 3) * 32;
    const int m0 = blockIdx.y * GBM, n0 = blockIdx.x * GBN;

    const uint32_t aoff = (uint32_t)((wm + (lane & 15)) * GPITCH + (lane >> 4) * 16);
    const uint32_t boff = (uint32_t)((wn + (lane & 7)) * GPITCH + ((lane >> 3) & 1) * 16
                                     + (lane >> 4) * (8 * GPITCH));

    float acc[4][4][4];
    #pragma unroll
    for (int i = 0; i < 4; i++)
        #pragma unroll
        for (int j = 0; j < 4; j++)
            #pragma unroll
            for (int q = 0; q < 4; q++) acc[i][j][q] = 0.0f;

    auto issue = [&](int kt, int buf) {
        const int k0 = kt * GBK;
        const uint32_t stg = sb + buf * GSTAGE;
        #pragma unroll
        for (int l = 0; l < 8; l++) {
            const int t = l >> 1;
            const int idx = tid + (l & 1) * 256;
            const int r = idx >> 2, c = idx & 3;
            const __nv_bfloat16* base = (t == 0) ? Ah : (t == 1) ? Al
                                        : (t == 2) ? Bh : Bl;
            const int grow = ((t < 2) ? m0 : n0) + r;
            cp_async16(stg + t * GTILE + r * GPITCH + c * 16,
                       base + (size_t)grow * CDIM + k0 + c * 8);
        }
        cp_commit();
    };

    issue(0, 0);
    for (int kt = 0; kt < NKT; kt++) {
        if (kt + 1 < NKT) { issue(kt + 1, (kt + 1) & 1); cp_wait1(); }
        else              { cp_wait0(); }
        __syncthreads();

        const uint32_t stg = sb + (kt & 1) * GSTAGE;
        const uint32_t a_hi = stg + 0 * GTILE + aoff;
        const uint32_t a_lo = stg + 1 * GTILE + aoff;
        const uint32_t b_hi = stg + 2 * GTILE + boff;
        const uint32_t b_lo = stg + 3 * GTILE + boff;

        #pragma unroll
        for (int ks = 0; ks < 2; ks++) {
            uint32_t ah[4][4], al[4][4];
            #pragma unroll
            for (int mt = 0; mt < 4; mt++) {
                ldm4(ah[mt], a_hi + mt * (16 * GPITCH) + ks * 32);
                ldm4(al[mt], a_lo + mt * (16 * GPITCH) + ks * 32);
            }
            #pragma unroll
            for (int p = 0; p < 2; p++) {
                uint32_t bh[4], bl[4];
                ldm4(bh, b_hi + p * (16 * GPITCH) + ks * 32);
                ldm4(bl, b_lo + p * (16 * GPITCH) + ks * 32);
                #pragma unroll
                for (int mt = 0; mt < 4; mt++) {
                    #pragma unroll
                    for (int q = 0; q < 2; q++) {
                        float* c = acc[mt][2 * p + q];
                        mma_bf16(c, ah[mt], bh[2 * q], bh[2 * q + 1]);
                        mma_bf16(c, ah[mt], bl[2 * q], bl[2 * q + 1]);
                        mma_bf16(c, al[mt], bh[2 * q], bh[2 * q + 1]);
                    }
                }
            }
        }
        __syncthreads();
    }

    const int erow = lane >> 2, ecol = (lane & 3) * 2;
    #pragma unroll
    for (int mt = 0; mt < 4; mt++) {
        #pragma unroll
        for (int nt = 0; nt < 4; nt++) {
            const int row = m0 + wm + mt * 16 + erow;
            const int col = n0 + wn + nt * 8 + ecol;
            const float2 bv = *reinterpret_cast<const float2*>(bias + col);
            const float v0x = acc[mt][nt][0] + bv.x;
            const float v0y = acc[mt][nt][1] + bv.y;
            const float v1x = acc[mt][nt][2] + bv.x;
            const float v1y = acc[mt][nt][3] + bv.y;
            if (SPLIT) {
                uint32_t hi, lo;
                split_pack2(v0x, v0y, hi, lo);
                *reinterpret_cast<uint32_t*>(Ch + (size_t)row * N + col) = hi;
                *reinterpret_cast<uint32_t*>(Cl + (size_t)row * N + col) = lo;
                split_pack2(v1x, v1y, hi, lo);
                *reinterpret_cast<uint32_t*>(Ch + (size_t)(row + 8) * N + col) = hi;
                *reinterpret_cast<uint32_t*>(Cl + (size_t)(row + 8) * N + col) = lo;
            } else {
                float2 v0; v0.x = v0x; v0.y = v0y;
                float2 v1; v1.x = v1x; v1.y = v1y;
                *reinterpret_cast<float2*>(C + (size_t)row * N + col) = v0;
                *reinterpret_cast<float2*>(C + (size_t)(row + 8) * N + col) = v1;
            }
        }
    }
}

// ---------------------------------------------------------------------------
// Flash attention via mma.sync (bf16 split, FA2 register-resident P).
// CTA = 128 q-rows x one (head, batch); 8 warps x 16 rows (full key span).
// S = QK^T 3-pass split; softmax quad-local; P kept in regs as A-fragments;
// PV 3-pass split with ldmatrix.trans V fragments. Writes y split (yh/yl).
// ---------------------------------------------------------------------------
__global__ __launch_bounds__(256, 2)
void flash_attn(const __nv_bfloat16* __restrict__ qkvh,
                const __nv_bfloat16* __restrict__ qkvl,
                const int* __restrict__ mask,
                __nv_bfloat16* __restrict__ yh, __nv_bfloat16* __restrict__ yl)
{
    extern __shared__ char smp[];
    const uint32_t sb = smem_u32(smp);
    const int qt = blockIdx.x, h = blockIdx.y, b = blockIdx.z;
    const int tid = threadIdx.x, lane = tid & 31, warp = tid >> 5;
    const int wm = warp * 16;
    const int q0 = qt * FBQ;
    const int seqbase = b * SEQ;

    // Load Q tile (128 x 64, hi/lo), natural layout, pitch 144B
    #pragma unroll
    for (int it = 0; it < 8; it++) {
        const int idx = tid + it * 256;
        const int r = idx >> 4, cc = idx & 15;
        const size_t go = (size_t)(seqbase + q0 + r) * QKVN + h * HDIM + cc * 4;
        *reinterpret_cast<uint2*>(smp + FQH + r * FPITCH + cc * 8) =
            *reinterpret_cast<const uint2*>(qkvh + go);
        *reinterpret_cast<uint2*>(smp + FQL + r * FPITCH + cc * 8) =
            *reinterpret_cast<const uint2*>(qkvl + go);
    }

    float oacc[8][4];
    #pragma unroll
    for (int nt = 0; nt < 8; nt++)
        #pragma unroll
        for (int q = 0; q < 4; q++) oacc[nt][q] = 0.0f;
    float m0 = -1e30f, m1 = -1e30f, l0 = 0.0f, l1 = 0.0f;
    const int rq0 = q0 + wm + (lane >> 2);   // in-sequence q position (row lo)
    const int rq1 = rq0 + 8;

    const uint32_t qhoff = sb + FQH + (wm + (lane & 15)) * FPITCH + (lane >> 4) * 16;
    const uint32_t qloff = sb + FQL + (wm + (lane & 15)) * FPITCH + (lane >> 4) * 16;
    const uint32_t kfrag = (uint32_t)(((lane & 7) + (lane >> 4) * 8) * FPITCH
                                      + ((lane >> 3) & 1) * 16);
    const uint32_t vfrag = (uint32_t)(((lane & 7) + ((lane >> 3) & 1) * 8) * FPITCH
                                      + (lane >> 4) * 16);

    const int nkt = 2 * qt + 2;
    for (int kt = 0; kt < nkt; kt++) {
        const int k0 = kt * 64;

        // Load K (natural) and V (natural; fragments via ldmatrix.trans)
        #pragma unroll
        for (int it = 0; it < 4; it++) {
            const int idx = tid + it * 256;
            const int r = idx >> 4, cc = idx & 15;
            const size_t gk = (size_t)(seqbase + k0 + r) * QKVN + CDIM + h * HDIM + cc * 4;
            *reinterpret_cast<uint2*>(smp + FKH + r * FPITCH + cc * 8) =
                *reinterpret_cast<const uint2*>(qkvh + gk);
            *reinterpret_cast<uint2*>(smp + FKL + r * FPITCH + cc * 8) =
                *reinterpret_cast<const uint2*>(qkvl + gk);
            *reinterpret_cast<uint2*>(smp + FVH + r * FPITCH + cc * 8) =
                *reinterpret_cast<const uint2*>(qkvh + gk + CDIM);
            *reinterpret_cast<uint2*>(smp + FVL + r * FPITCH + cc * 8) =
                *reinterpret_cast<const uint2*>(qkvl + gk + CDIM);
        }
        if (tid < 64)
            reinterpret_cast<float*>(smp + FMASK)[tid] =
                (__ldg(&mask[seqbase + k0 + tid]) != 0) ? 0.0f : -2e30f;
        __syncthreads();

        if (k0 <= q0 + wm + 15) {          // warp has at least one valid key
            // ---- S = Q K^T (3-pass split) ----
            float sacc[8][4];
            #pragma unroll
            for (int nt = 0; nt < 8; nt++)
                #pragma unroll
                for (int q = 0; q < 4; q++) sacc[nt][q] = 0.0f;

            #pragma unroll
            for (int ks = 0; ks < 4; ks++) {
                uint32_t qhf[4], qlf[4];
                ldm4(qhf, qhoff + ks * 32);
                ldm4(qlf, qloff + ks * 32);
                #pragma unroll
                for (int g = 0; g < 4; g++) {
                    uint32_t khf[4], klf[4];
                    const uint32_t ka = g * (16 * FPITCH) + kfrag + ks * 32;
                    ldm4(khf, sb + FKH + ka);
                    ldm4(klf, sb + FKL + ka);
                    #pragma unroll
                    for (int q = 0; q < 2; q++) {
                        float* c = sacc[2 * g + q];
                        mma_bf16(c, qhf, khf[2 * q], khf[2 * q + 1]);
                        mma_bf16(c, qhf, klf[2 * q], klf[2 * q + 1]);
                        mma_bf16(c, qlf, khf[2 * q], khf[2 * q + 1]);
                    }
                }
            }

            // ---- mask + online softmax (quad-local rows) ----
            const float* madd = reinterpret_cast<const float*>(smp + FMASK);
            float mx0 = -1e30f, mx1 = -1e30f;
            #pragma unroll
            for (int nt = 0; nt < 8; nt++) {
                const int kc = nt * 8 + (lane & 3) * 2;
                const int gk0 = k0 + kc, gk1 = gk0 + 1;
                const float a0 = madd[kc], a1 = madd[kc + 1];
                const float s0 = (gk0 <= rq0) ? sacc[nt][0] * 0.125f + a0 : -1e30f;
                const float s1 = (gk1 <= rq0) ? sacc[nt][1] * 0.125f + a1 : -1e30f;
                const float s2 = (gk0 <= rq1) ? sacc[nt][2] * 0.125f + a0 : -1e30f;
                const float s3 = (gk1 <= rq1) ? sacc[nt][3] * 0.125f + a1 : -1e30f;
                sacc[nt][0] = s0; sacc[nt][1] = s1; sacc[nt][2] = s2; sacc[nt][3] = s3;
                mx0 = fmaxf(mx0, fmaxf(s0, s1));
                mx1 = fmaxf(mx1, fmaxf(s2, s3));
            }
            mx0 = fmaxf(mx0, __shfl_xor_sync(0xffffffffu, mx0, 1));
            mx0 = fmaxf(mx0, __shfl_xor_sync(0xffffffffu, mx0, 2));
            mx1 = fmaxf(mx1, __shfl_xor_sync(0xffffffffu, mx1, 1));
            mx1 = fmaxf(mx1, __shfl_xor_sync(0xffffffffu, mx1, 2));
            const float mn0 = fmaxf(fmaxf(m0, mx0), -1e29f);
            const float mn1 = fmaxf(fmaxf(m1, mx1), -1e29f);
            const float al0 = __expf(m0 - mn0), al1 = __expf(m1 - mn1);
            m0 = mn0; m1 = mn1;
            float sum0 = 0.0f, sum1 = 0.0f;
            #pragma unroll
            for (int nt = 0; nt < 8; nt++) {
                float p;
                p = __expf(sacc[nt][0] - mn0); sacc[nt][0] = p; sum0 += p;
                p = __expf(sacc[nt][1] - mn0); sacc[nt][1] = p; sum0 += p;
                p = __expf(sacc[nt][2] - mn1); sacc[nt][2] = p; sum1 += p;
                p = __expf(sacc[nt][3] - mn1); sacc[nt][3] = p; sum1 += p;
            }
            sum0 += __shfl_xor_sync(0xffffffffu, sum0, 1);
            sum0 += __shfl_xor_sync(0xffffffffu, sum0, 2);
            sum1 += __shfl_xor_sync(0xffffffffu, sum1, 1);
            sum1 += __shfl_xor_sync(0xffffffffu, sum1, 2);
            l0 = l0 * al0 + sum0;
            l1 = l1 * al1 + sum1;
            #pragma unroll
            for (int nt = 0; nt < 8; nt++) {
                oacc[nt][0] *= al0; oacc[nt][1] *= al0;
                oacc[nt][2] *= al1; oacc[nt][3] *= al1;
            }

            // ---- O += P V (3-pass split; P regs are A-fragments) ----
            #pragma unroll
            for (int ks = 0; ks < 4; ks++) {
                uint32_t pha[4], pla[4];
                split_pack2(sacc[2 * ks][0],     sacc[2 * ks][1],     pha[0], pla[0]);
                split_pack2(sacc[2 * ks][2],     sacc[2 * ks][3],     pha[1], pla[1]);
                split_pack2(sacc[2 * ks + 1][0], sacc[2 * ks + 1][1], pha[2], pla[2]);
                split_pack2(sacc[2 * ks + 1][2], sacc[2 * ks + 1][3], pha[3], pla[3]);
                #pragma unroll
                for (int g = 0; g < 4; g++) {
                    uint32_t vhf[4], vlf[4];
                    const uint32_t va = (ks * 16) * FPITCH + vfrag + g * 32;
                    ldm4t(vhf, sb + FVH + va);
                    ldm4t(vlf, sb + FVL + va);
                    #pragma unroll
                    for (int q = 0; q < 2; q++) {
                        float* c = oacc[2 * g + q];
                        mma_bf16(c, pha, vhf[2 * q], vhf[2 * q + 1]);
                        mma_bf16(c, pha, vlf[2 * q], vlf[2 * q + 1]);
                        mma_bf16(c, pla, vhf[2 * q], vhf[2 * q + 1]);
                    }
                }
            }
        }
        __syncthreads();
    }

    // Epilogue: normalize, split, write y (hi/lo)
    const float inv0 = 1.0f / l0, inv1 = 1.0f / l1;
    const int row0 = seqbase + q0 + wm + (lane >> 2);
    #pragma unroll
    for (int nt = 0; nt < 8; nt++) {
        const int col = h * HDIM + nt * 8 + (lane & 3) * 2;
        uint32_t hi, lo;
        split_pack2(oacc[nt][0] * inv0, oacc[nt][1] * inv0, hi, lo);
        *reinterpret_cast<uint32_t*>(yh + (size_t)row0 * CDIM + col) = hi;
        *reinterpret_cast<uint32_t*>(yl + (size_t)row0 * CDIM + col) = lo;
        split_pack2(oacc[nt][2] * inv1, oacc[nt][3] * inv1, hi, lo);
        *reinterpret_cast<uint32_t*>(yh + (size_t)(row0 + 8) * CDIM + col) = hi;
        *reinterpret_cast<uint32_t*>(yl + (size_t)(row0 + 8) * CDIM + col) = lo;
    }
}

// ---------------------------------------------------------------------------
// Launch
// ---------------------------------------------------------------------------
extern "C" void kernel_launch(void* const* d_in, const int* in_sizes, int n_in,
                              void* d_out, int out_size)
{
    const float* x     = (const float*)d_in[0];
    const int*   mask  = (const int*)  d_in[1];
    const float* Wqkv  = (const float*)d_in[2];
    const float* bqkv  = (const float*)d_in[3];
    const float* Wproj = (const float*)d_in[4];
    const float* bproj = (const float*)d_in[5];
    float* out = (float*)d_out;

    __nv_bfloat16 *qkvh, *qkvl, *xh, *xl, *yh, *yl, *wqh, *wql, *wph, *wpl;
    cudaGetSymbolAddress((void**)&qkvh, g_qkvh);
    cudaGetSymbolAddress((void**)&qkvl, g_qkvl);
    cudaGetSymbolAddress((void**)&xh, g_xh);
    cudaGetSymbolAddress((void**)&xl, g_xl);
    cudaGetSymbolAddress((void**)&yh, g_yh);
    cudaGetSymbolAddress((void**)&yl, g_yl);
    cudaGetSymbolAddress((void**)&wqh, g_wqh);
    cudaGetSymbolAddress((void**)&wql, g_wql);
    cudaGetSymbolAddress((void**)&wph, g_wph);
    cudaGetSymbolAddress((void**)&wpl, g_wpl);

    cudaFuncSetAttribute(gemm_bf16s<0>,
                         cudaFuncAttributeMaxDynamicSharedMemorySize, GSMEM);
    cudaFuncSetAttribute(gemm_bf16s<1>,
                         cudaFuncAttributeMaxDynamicSharedMemorySize, GSMEM);
    cudaFuncSetAttribute(flash_attn,
                         cudaFuncAttributeMaxDynamicSharedMemorySize, FSMEM);

    // Conversions
    split4<<<(MROWS * CDIM / 4 + 255) / 256, 256>>>(x, xh, xl, MROWS * CDIM / 4);
    transpose_split<<<dim3(QKVN / 32, CDIM / 32), dim3(32, 8)>>>(Wqkv, wqh, wql, QKVN);
    transpose_split<<<dim3(CDIM / 32, CDIM / 32), dim3(32, 8)>>>(Wproj, wph, wpl, CDIM);

    // 1) QKV GEMM -> split bf16 qkv
    gemm_bf16s<1><<<dim3(QKVN / GBN, MROWS / GBM), 256, GSMEM>>>(
        xh, xl, wqh, wql, bqkv, nullptr, qkvh, qkvl, QKVN);

    // 2) Flash attention (tensor cores) -> split bf16 y
    flash_attn<<<dim3(SEQ / FBQ, NHEAD, BATCH), 256, FSMEM>>>(
        qkvh, qkvl, mask, yh, yl);

    // 3) Projection GEMM -> fp32 out
    gemm_bf16s<0><<<dim3(CDIM / GBN, MROWS / GBM), 256, GSMEM>>>(
        yh, yl, wph, wpl, bproj, out, nullptr, nullptr, CDIM);
}

// round 9
// speedup vs baseline: 2.9034x; 1.0017x over previous
#include <cuda_runtime.h>
#include <cuda_bf16.h>
#include <cstdint>

// ---------------------------------------------------------------------------
// Problem constants
// ---------------------------------------------------------------------------
#define BATCH 2
#define SEQ   2048
#define CDIM  1024
#define NHEAD 16
#define HDIM  64
#define MROWS (BATCH * SEQ)     // 4096
#define QKVN  (3 * CDIM)        // 3072

// GEMM tiling (warp-level mma.sync path; tcgen05 rejected by compute_103 PTX)
#define GBM 128
#define GBN 128
#define GBK 32
#define GPITCH 80                      // 64B data + 16B pad; 16B-aligned rows
#define GTILE  (128 * GPITCH)
#define GSTAGE (4 * GTILE)
#define GSMEM  (2 * GSTAGE)            // 81920 B
#define NKT    (CDIM / GBK)

// Flash tiling: 128 q-rows x 64-key tiles, 8 warps x 16 rows
#define FBQ    128
#define FPITCH 144                     // 64 bf16 (128B) + 16B pad
#define FQH 0
#define FQL (128 * FPITCH)
#define FKH (2 * 128 * FPITCH)
#define FKL (FKH + 64 * FPITCH)
#define FVH (FKL + 64 * FPITCH)
#define FVL (FVH + 64 * FPITCH)
#define FMASK (FVL + 64 * FPITCH)
#define FSMEM (FMASK + 64 * 4)         // 73984 B

// ---------------------------------------------------------------------------
// Scratch (allocation-free __device__ globals)
// ---------------------------------------------------------------------------
__device__ __align__(16) __nv_bfloat16 g_qkvh[MROWS * QKVN];
__device__ __align__(16) __nv_bfloat16 g_qkvl[MROWS * QKVN];
__device__ __align__(16) __nv_bfloat16 g_xh[MROWS * CDIM];
__device__ __align__(16) __nv_bfloat16 g_xl[MROWS * CDIM];
__device__ __align__(16) __nv_bfloat16 g_yh[MROWS * CDIM];
__device__ __align__(16) __nv_bfloat16 g_yl[MROWS * CDIM];
__device__ __align__(16) __nv_bfloat16 g_wqh[QKVN * CDIM];    // W^T [3072][1024]
__device__ __align__(16) __nv_bfloat16 g_wql[QKVN * CDIM];
__device__ __align__(16) __nv_bfloat16 g_wph[CDIM * CDIM];    // W^T [1024][1024]
__device__ __align__(16) __nv_bfloat16 g_wpl[CDIM * CDIM];

// ---------------------------------------------------------------------------
// PTX helpers (sm_80-era: valid on compute_103)
// ---------------------------------------------------------------------------
__device__ __forceinline__ uint32_t smem_u32(const void* p) {
    uint32_t a;
    asm("{ .reg .u64 t; cvta.to.shared.u64 t, %1; cvt.u32.u64 %0, t; }"
        : "=r"(a) : "l"(p));
    return a;
}
__device__ __forceinline__ void cp_async16(uint32_t dst, const void* src) {
    asm volatile("cp.async.cg.shared.global [%0], [%1], 16;"
                 :: "r"(dst), "l"(src) : "memory");
}
__device__ __forceinline__ void cp_commit() {
    asm volatile("cp.async.commit_group;" ::: "memory");
}
__device__ __forceinline__ void cp_wait1() {
    asm volatile("cp.async.wait_group 1;" ::: "memory");
}
__device__ __forceinline__ void cp_wait0() {
    asm volatile("cp.async.wait_group 0;" ::: "memory");
}
__device__ __forceinline__ void ldm4(uint32_t* r, uint32_t addr) {
    asm volatile("ldmatrix.sync.aligned.m8n8.x4.shared.b16 {%0,%1,%2,%3}, [%4];"
                 : "=r"(r[0]), "=r"(r[1]), "=r"(r[2]), "=r"(r[3]) : "r"(addr));
}
__device__ __forceinline__ void ldm4t(uint32_t* r, uint32_t addr) {
    asm volatile("ldmatrix.sync.aligned.m8n8.x4.trans.shared.b16 {%0,%1,%2,%3}, [%4];"
                 : "=r"(r[0]), "=r"(r[1]), "=r"(r[2]), "=r"(r[3]) : "r"(addr));
}
__device__ __forceinline__ void mma_bf16(float* c, const uint32_t* a,
                                         uint32_t b0, uint32_t b1) {
    asm volatile(
        "mma.sync.aligned.m16n8k16.row.col.f32.bf16.bf16.f32 "
        "{%0,%1,%2,%3}, {%4,%5,%6,%7}, {%8,%9}, {%0,%1,%2,%3};"
        : "+f"(c[0]), "+f"(c[1]), "+f"(c[2]), "+f"(c[3])
        : "r"(a[0]), "r"(a[1]), "r"(a[2]), "r"(a[3]), "r"(b0), "r"(b1));
}

// ---------------------------------------------------------------------------
// fp32 -> bf16 split helpers / conversion kernels
// ---------------------------------------------------------------------------
__device__ __forceinline__ void split_bf16(float a, __nv_bfloat16& h, __nv_bfloat16& l) {
    h = __float2bfloat16(a);
    l = __float2bfloat16(a - __bfloat162float(h));
}
__device__ __forceinline__ void split_pack2(float x, float y, uint32_t& hi, uint32_t& lo) {
    __nv_bfloat16 hx, lx, hy, ly;
    split_bf16(x, hx, lx);
    split_bf16(y, hy, ly);
    __nv_bfloat162 h2 = __halves2bfloat162(hx, hy);
    __nv_bfloat162 l2 = __halves2bfloat162(lx, ly);
    hi = *reinterpret_cast<uint32_t*>(&h2);
    lo = *reinterpret_cast<uint32_t*>(&l2);
}

__global__ __launch_bounds__(256)
void split4(const float* __restrict__ in, __nv_bfloat16* __restrict__ hi,
            __nv_bfloat16* __restrict__ lo, int n4)
{
    int i = blockIdx.x * blockDim.x + threadIdx.x;
    if (i >= n4) return;
    float4 v = reinterpret_cast<const float4*>(in)[i];
    uint32_t h0, l0, h1, l1;
    split_pack2(v.x, v.y, h0, l0);
    split_pack2(v.z, v.w, h1, l1);
    reinterpret_cast<uint32_t*>(hi)[2 * i]     = h0;
    reinterpret_cast<uint32_t*>(hi)[2 * i + 1] = h1;
    reinterpret_cast<uint32_t*>(lo)[2 * i]     = l0;
    reinterpret_cast<uint32_t*>(lo)[2 * i + 1] = l1;
}

// Transpose + split: W[1024][Ncols] fp32 -> T_hi/lo [Ncols][1024] bf16
__global__ __launch_bounds__(256)
void transpose_split(const float* __restrict__ W, __nv_bfloat16* __restrict__ Th,
                     __nv_bfloat16* __restrict__ Tl, int Ncols)
{
    __shared__ float t[32][33];
    const int tx = threadIdx.x, ty = threadIdx.y;
    const int n = blockIdx.x * 32 + tx;
    const int k0 = blockIdx.y * 32;
    #pragma unroll
    for (int j = 0; j < 4; j++)
        t[ty + j * 8][tx] = W[(size_t)(k0 + ty + j * 8) * Ncols + n];
    __syncthreads();
    const int nr = blockIdx.x * 32;
    #pragma unroll
    for (int j = 0; j < 4; j++) {
        float a = t[tx][ty + j * 8];
        __nv_bfloat16 h, l;
        split_bf16(a, h, l);
        size_t o = (size_t)(nr + ty + j * 8) * CDIM + k0 + tx;
        Th[o] = h; Tl[o] = l;
    }
}

// ---------------------------------------------------------------------------
// bf16 split GEMM via mma.sync: C = (Ah+Al) @ (Bh+Bl)^T + bias
// Pass-major MMA ordering: each split pass sweeps all 8 independent
// accumulators before the next pass touches them (chain distance 8).
// ---------------------------------------------------------------------------
template<int SPLIT>
__global__ __launch_bounds__(256, 2)
void gemm_bf16s(const __nv_bfloat16* __restrict__ Ah, const __nv_bfloat16* __restrict__ Al,
                const __nv_bfloat16* __restrict__ Bh, const __nv_bfloat16* __restrict__ Bl,
                const float* __restrict__ bias, float* __restrict__ C,
                __nv_bfloat16* __restrict__ Ch, __nv_bfloat16* __restrict__ Cl, int N)
{
    extern __shared__ char sm[];
    const uint32_t sb = smem_u32(sm);
    const int tid = threadIdx.x;
    const int lane = tid & 31, warp = tid >> 5;
    const int wm = (warp >> 2) * 64;
    const int wn = (warp & 3) * 32;
    const int m0 = blockIdx.y * GBM, n0 = blockIdx.x * GBN;

    const uint32_t aoff = (uint32_t)((wm + (lane & 15)) * GPITCH + (lane >> 4) * 16);
    const uint32_t boff = (uint32_t)((wn + (lane & 7)) * GPITCH + ((lane >> 3) & 1) * 16
                                     + (lane >> 4) * (8 * GPITCH));

    float acc[4][4][4];
    #pragma unroll
    for (int i = 0; i < 4; i++)
        #pragma unroll
        for (int j = 0; j < 4; j++)
            #pragma unroll
            for (int q = 0; q < 4; q++) acc[i][j][q] = 0.0f;

    auto issue = [&](int kt, int buf) {
        const int k0 = kt * GBK;
        const uint32_t stg = sb + buf * GSTAGE;
        #pragma unroll
        for (int l = 0; l < 8; l++) {
            const int t = l >> 1;
            const int idx = tid + (l & 1) * 256;
            const int r = idx >> 2, c = idx & 3;
            const __nv_bfloat16* base = (t == 0) ? Ah : (t == 1) ? Al
                                        : (t == 2) ? Bh : Bl;
            const int grow = ((t < 2) ? m0 : n0) + r;
            cp_async16(stg + t * GTILE + r * GPITCH + c * 16,
                       base + (size_t)grow * CDIM + k0 + c * 8);
        }
        cp_commit();
    };

    issue(0, 0);
    for (int kt = 0; kt < NKT; kt++) {
        if (kt + 1 < NKT) { issue(kt + 1, (kt + 1) & 1); cp_wait1(); }
        else              { cp_wait0(); }
        __syncthreads();

        const uint32_t stg = sb + (kt & 1) * GSTAGE;
        const uint32_t a_hi = stg + 0 * GTILE + aoff;
        const uint32_t a_lo = stg + 1 * GTILE + aoff;
        const uint32_t b_hi = stg + 2 * GTILE + boff;
        const uint32_t b_lo = stg + 3 * GTILE + boff;

        #pragma unroll
        for (int ks = 0; ks < 2; ks++) {
            uint32_t ah[4][4], al[4][4];
            #pragma unroll
            for (int mt = 0; mt < 4; mt++) {
                ldm4(ah[mt], a_hi + mt * (16 * GPITCH) + ks * 32);
                ldm4(al[mt], a_lo + mt * (16 * GPITCH) + ks * 32);
            }
            #pragma unroll
            for (int p = 0; p < 2; p++) {
                uint32_t bh[4], bl[4];
                ldm4(bh, b_hi + p * (16 * GPITCH) + ks * 32);
                ldm4(bl, b_lo + p * (16 * GPITCH) + ks * 32);
                // pass hh: 8 independent accumulators back-to-back
                #pragma unroll
                for (int mt = 0; mt < 4; mt++)
                    #pragma unroll
                    for (int q = 0; q < 2; q++)
                        mma_bf16(acc[mt][2 * p + q], ah[mt], bh[2 * q], bh[2 * q + 1]);
                // pass hl
                #pragma unroll
                for (int mt = 0; mt < 4; mt++)
                    #pragma unroll
                    for (int q = 0; q < 2; q++)
                        mma_bf16(acc[mt][2 * p + q], ah[mt], bl[2 * q], bl[2 * q + 1]);
                // pass lh
                #pragma unroll
                for (int mt = 0; mt < 4; mt++)
                    #pragma unroll
                    for (int q = 0; q < 2; q++)
                        mma_bf16(acc[mt][2 * p + q], al[mt], bh[2 * q], bh[2 * q + 1]);
            }
        }
        __syncthreads();
    }

    const int erow = lane >> 2, ecol = (lane & 3) * 2;
    #pragma unroll
    for (int mt = 0; mt < 4; mt++) {
        #pragma unroll
        for (int nt = 0; nt < 4; nt++) {
            const int row = m0 + wm + mt * 16 + erow;
            const int col = n0 + wn + nt * 8 + ecol;
            const float2 bv = *reinterpret_cast<const float2*>(bias + col);
            const float v0x = acc[mt][nt][0] + bv.x;
            const float v0y = acc[mt][nt][1] + bv.y;
            const float v1x = acc[mt][nt][2] + bv.x;
            const float v1y = acc[mt][nt][3] + bv.y;
            if (SPLIT) {
                uint32_t hi, lo;
                split_pack2(v0x, v0y, hi, lo);
                *reinterpret_cast<uint32_t*>(Ch + (size_t)row * N + col) = hi;
                *reinterpret_cast<uint32_t*>(Cl + (size_t)row * N + col) = lo;
                split_pack2(v1x, v1y, hi, lo);
                *reinterpret_cast<uint32_t*>(Ch + (size_t)(row + 8) * N + col) = hi;
                *reinterpret_cast<uint32_t*>(Cl + (size_t)(row + 8) * N + col) = lo;
            } else {
                float2 v0; v0.x = v0x; v0.y = v0y;
                float2 v1; v1.x = v1x; v1.y = v1y;
                *reinterpret_cast<float2*>(C + (size_t)row * N + col) = v0;
                *reinterpret_cast<float2*>(C + (size_t)(row + 8) * N + col) = v1;
            }
        }
    }
}

// ---------------------------------------------------------------------------
// Flash attention via mma.sync (bf16 split, FA2 register-resident P).
// Pass-major MMA ordering with K/V fragments hoisted 2 g-groups at a time
// (chain distance 4).
// ---------------------------------------------------------------------------
__global__ __launch_bounds__(256, 2)
void flash_attn(const __nv_bfloat16* __restrict__ qkvh,
                const __nv_bfloat16* __restrict__ qkvl,
                const int* __restrict__ mask,
                __nv_bfloat16* __restrict__ yh, __nv_bfloat16* __restrict__ yl)
{
    extern __shared__ char smp[];
    const uint32_t sb = smem_u32(smp);
    const int qt = blockIdx.x, h = blockIdx.y, b = blockIdx.z;
    const int tid = threadIdx.x, lane = tid & 31, warp = tid >> 5;
    const int wm = warp * 16;
    const int q0 = qt * FBQ;
    const int seqbase = b * SEQ;

    #pragma unroll
    for (int it = 0; it < 8; it++) {
        const int idx = tid + it * 256;
        const int r = idx >> 4, cc = idx & 15;
        const size_t go = (size_t)(seqbase + q0 + r) * QKVN + h * HDIM + cc * 4;
        *reinterpret_cast<uint2*>(smp + FQH + r * FPITCH + cc * 8) =
            *reinterpret_cast<const uint2*>(qkvh + go);
        *reinterpret_cast<uint2*>(smp + FQL + r * FPITCH + cc * 8) =
            *reinterpret_cast<const uint2*>(qkvl + go);
    }

    float oacc[8][4];
    #pragma unroll
    for (int nt = 0; nt < 8; nt++)
        #pragma unroll
        for (int q = 0; q < 4; q++) oacc[nt][q] = 0.0f;
    float m0 = -1e30f, m1 = -1e30f, l0 = 0.0f, l1 = 0.0f;
    const int rq0 = q0 + wm + (lane >> 2);
    const int rq1 = rq0 + 8;

    const uint32_t qhoff = sb + FQH + (wm + (lane & 15)) * FPITCH + (lane >> 4) * 16;
    const uint32_t qloff = sb + FQL + (wm + (lane & 15)) * FPITCH + (lane >> 4) * 16;
    const uint32_t kfrag = (uint32_t)(((lane & 7) + (lane >> 4) * 8) * FPITCH
                                      + ((lane >> 3) & 1) * 16);
    const uint32_t vfrag = (uint32_t)(((lane & 7) + ((lane >> 3) & 1) * 8) * FPITCH
                                      + (lane >> 4) * 16);

    const int nkt = 2 * qt + 2;
    for (int kt = 0; kt < nkt; kt++) {
        const int k0 = kt * 64;

        #pragma unroll
        for (int it = 0; it < 4; it++) {
            const int idx = tid + it * 256;
            const int r = idx >> 4, cc = idx & 15;
            const size_t gk = (size_t)(seqbase + k0 + r) * QKVN + CDIM + h * HDIM + cc * 4;
            *reinterpret_cast<uint2*>(smp + FKH + r * FPITCH + cc * 8) =
                *reinterpret_cast<const uint2*>(qkvh + gk);
            *reinterpret_cast<uint2*>(smp + FKL + r * FPITCH + cc * 8) =
                *reinterpret_cast<const uint2*>(qkvl + gk);
            *reinterpret_cast<uint2*>(smp + FVH + r * FPITCH + cc * 8) =
                *reinterpret_cast<const uint2*>(qkvh + gk + CDIM);
            *reinterpret_cast<uint2*>(smp + FVL + r * FPITCH + cc * 8) =
                *reinterpret_cast<const uint2*>(qkvl + gk + CDIM);
        }
        if (tid < 64)
            reinterpret_cast<float*>(smp + FMASK)[tid] =
                (__ldg(&mask[seqbase + k0 + tid]) != 0) ? 0.0f : -2e30f;
        __syncthreads();

        if (k0 <= q0 + wm + 15) {
            // ---- S = Q K^T (3-pass split, pass-major) ----
            float sacc[8][4];
            #pragma unroll
            for (int nt = 0; nt < 8; nt++)
                #pragma unroll
                for (int q = 0; q < 4; q++) sacc[nt][q] = 0.0f;

            #pragma unroll
            for (int ks = 0; ks < 4; ks++) {
                uint32_t qhf[4], qlf[4];
                ldm4(qhf, qhoff + ks * 32);
                ldm4(qlf, qloff + ks * 32);
                #pragma unroll
                for (int gg = 0; gg < 2; gg++) {
                    uint32_t khf[2][4], klf[2][4];
                    #pragma unroll
                    for (int g2 = 0; g2 < 2; g2++) {
                        const uint32_t ka = (2 * gg + g2) * (16 * FPITCH) + kfrag + ks * 32;
                        ldm4(khf[g2], sb + FKH + ka);
                        ldm4(klf[g2], sb + FKL + ka);
                    }
                    // pass hh (4 independent accs), then hl, then lh
                    #pragma unroll
                    for (int g2 = 0; g2 < 2; g2++)
                        #pragma unroll
                        for (int q = 0; q < 2; q++)
                            mma_bf16(sacc[2 * (2 * gg + g2) + q], qhf,
                                     khf[g2][2 * q], khf[g2][2 * q + 1]);
                    #pragma unroll
                    for (int g2 = 0; g2 < 2; g2++)
                        #pragma unroll
                        for (int q = 0; q < 2; q++)
                            mma_bf16(sacc[2 * (2 * gg + g2) + q], qhf,
                                     klf[g2][2 * q], klf[g2][2 * q + 1]);
                    #pragma unroll
                    for (int g2 = 0; g2 < 2; g2++)
                        #pragma unroll
                        for (int q = 0; q < 2; q++)
                            mma_bf16(sacc[2 * (2 * gg + g2) + q], qlf,
                                     khf[g2][2 * q], khf[g2][2 * q + 1]);
                }
            }

            // ---- mask + online softmax (quad-local rows) ----
            const float* madd = reinterpret_cast<const float*>(smp + FMASK);
            float mx0 = -1e30f, mx1 = -1e30f;
            #pragma unroll
            for (int nt = 0; nt < 8; nt++) {
                const int kc = nt * 8 + (lane & 3) * 2;
                const int gk0 = k0 + kc, gk1 = gk0 + 1;
                const float a0 = madd[kc], a1 = madd[kc + 1];
                const float s0 = (gk0 <= rq0) ? sacc[nt][0] * 0.125f + a0 : -1e30f;
                const float s1 = (gk1 <= rq0) ? sacc[nt][1] * 0.125f + a1 : -1e30f;
                const float s2 = (gk0 <= rq1) ? sacc[nt][2] * 0.125f + a0 : -1e30f;
                const float s3 = (gk1 <= rq1) ? sacc[nt][3] * 0.125f + a1 : -1e30f;
                sacc[nt][0] = s0; sacc[nt][1] = s1; sacc[nt][2] = s2; sacc[nt][3] = s3;
                mx0 = fmaxf(mx0, fmaxf(s0, s1));
                mx1 = fmaxf(mx1, fmaxf(s2, s3));
            }
            mx0 = fmaxf(mx0, __shfl_xor_sync(0xffffffffu, mx0, 1));
            mx0 = fmaxf(mx0, __shfl_xor_sync(0xffffffffu, mx0, 2));
            mx1 = fmaxf(mx1, __shfl_xor_sync(0xffffffffu, mx1, 1));
            mx1 = fmaxf(mx1, __shfl_xor_sync(0xffffffffu, mx1, 2));
            const float mn0 = fmaxf(fmaxf(m0, mx0), -1e29f);
            const float mn1 = fmaxf(fmaxf(m1, mx1), -1e29f);
            const float al0 = __expf(m0 - mn0), al1 = __expf(m1 - mn1);
            m0 = mn0; m1 = mn1;
            float sum0 = 0.0f, sum1 = 0.0f;
            #pragma unroll
            for (int nt = 0; nt < 8; nt++) {
                float p;
                p = __expf(sacc[nt][0] - mn0); sacc[nt][0] = p; sum0 += p;
                p = __expf(sacc[nt][1] - mn0); sacc[nt][1] = p; sum0 += p;
                p = __expf(sacc[nt][2] - mn1); sacc[nt][2] = p; sum1 += p;
                p = __expf(sacc[nt][3] - mn1); sacc[nt][3] = p; sum1 += p;
            }
            sum0 += __shfl_xor_sync(0xffffffffu, sum0, 1);
            sum0 += __shfl_xor_sync(0xffffffffu, sum0, 2);
            sum1 += __shfl_xor_sync(0xffffffffu, sum1, 1);
            sum1 += __shfl_xor_sync(0xffffffffu, sum1, 2);
            l0 = l0 * al0 + sum0;
            l1 = l1 * al1 + sum1;
            #pragma unroll
            for (int nt = 0; nt < 8; nt++) {
                oacc[nt][0] *= al0; oacc[nt][1] *= al0;
                oacc[nt][2] *= al1; oacc[nt][3] *= al1;
            }

            // ---- O += P V (3-pass split, pass-major) ----
            #pragma unroll
            for (int ks = 0; ks < 4; ks++) {
                uint32_t pha[4], pla[4];
                split_pack2(sacc[2 * ks][0],     sacc[2 * ks][1],     pha[0], pla[0]);
                split_pack2(sacc[2 * ks][2],     sacc[2 * ks][3],     pha[1], pla[1]);
                split_pack2(sacc[2 * ks + 1][0], sacc[2 * ks + 1][1], pha[2], pla[2]);
                split_pack2(sacc[2 * ks + 1][2], sacc[2 * ks + 1][3], pha[3], pla[3]);
                #pragma unroll
                for (int gg = 0; gg < 2; gg++) {
                    uint32_t vhf[2][4], vlf[2][4];
                    #pragma unroll
                    for (int g2 = 0; g2 < 2; g2++) {
                        const uint32_t va = (ks * 16) * FPITCH + vfrag
                                            + (2 * gg + g2) * 32;
                        ldm4t(vhf[g2], sb + FVH + va);
                        ldm4t(vlf[g2], sb + FVL + va);
                    }
                    #pragma unroll
                    for (int g2 = 0; g2 < 2; g2++)
                        #pragma unroll
                        for (int q = 0; q < 2; q++)
                            mma_bf16(oacc[2 * (2 * gg + g2) + q], pha,
                                     vhf[g2][2 * q], vhf[g2][2 * q + 1]);
                    #pragma unroll
                    for (int g2 = 0; g2 < 2; g2++)
                        #pragma unroll
                        for (int q = 0; q < 2; q++)
                            mma_bf16(oacc[2 * (2 * gg + g2) + q], pha,
                                     vlf[g2][2 * q], vlf[g2][2 * q + 1]);
                    #pragma unroll
                    for (int g2 = 0; g2 < 2; g2++)
                        #pragma unroll
                        for (int q = 0; q < 2; q++)
                            mma_bf16(oacc[2 * (2 * gg + g2) + q], pla,
                                     vhf[g2][2 * q], vhf[g2][2 * q + 1]);
                }
            }
        }
        __syncthreads();
    }

    const float inv0 = 1.0f / l0, inv1 = 1.0f / l1;
    const int row0 = seqbase + q0 + wm + (lane >> 2);
    #pragma unroll
    for (int nt = 0; nt < 8; nt++) {
        const int col = h * HDIM + nt * 8 + (lane & 3) * 2;
        uint32_t hi, lo;
        split_pack2(oacc[nt][0] * inv0, oacc[nt][1] * inv0, hi, lo);
        *reinterpret_cast<uint32_t*>(yh + (size_t)row0 * CDIM + col) = hi;
        *reinterpret_cast<uint32_t*>(yl + (size_t)row0 * CDIM + col) = lo;
        split_pack2(oacc[nt][2] * inv1, oacc[nt][3] * inv1, hi, lo);
        *reinterpret_cast<uint32_t*>(yh + (size_t)(row0 + 8) * CDIM + col) = hi;
        *reinterpret_cast<uint32_t*>(yl + (size_t)(row0 + 8) * CDIM + col) = lo;
    }
}

// ---------------------------------------------------------------------------
// Launch
// ---------------------------------------------------------------------------
extern "C" void kernel_launch(void* const* d_in, const int* in_sizes, int n_in,
                              void* d_out, int out_size)
{
    const float* x     = (const float*)d_in[0];
    const int*   mask  = (const int*)  d_in[1];
    const float* Wqkv  = (const float*)d_in[2];
    const float* bqkv  = (const float*)d_in[3];
    const float* Wproj = (const float*)d_in[4];
    const float* bproj = (const float*)d_in[5];
    float* out = (float*)d_out;

    __nv_bfloat16 *qkvh, *qkvl, *xh, *xl, *yh, *yl, *wqh, *wql, *wph, *wpl;
    cudaGetSymbolAddress((void**)&qkvh, g_qkvh);
    cudaGetSymbolAddress((void**)&qkvl, g_qkvl);
    cudaGetSymbolAddress((void**)&xh, g_xh);
    cudaGetSymbolAddress((void**)&xl, g_xl);
    cudaGetSymbolAddress((void**)&yh, g_yh);
    cudaGetSymbolAddress((void**)&yl, g_yl);
    cudaGetSymbolAddress((void**)&wqh, g_wqh);
    cudaGetSymbolAddress((void**)&wql, g_wql);
    cudaGetSymbolAddress((void**)&wph, g_wph);
    cudaGetSymbolAddress((void**)&wpl, g_wpl);

    cudaFuncSetAttribute(gemm_bf16s<0>,
                         cudaFuncAttributeMaxDynamicSharedMemorySize, GSMEM);
    cudaFuncSetAttribute(gemm_bf16s<1>,
                         cudaFuncAttributeMaxDynamicSharedMemorySize, GSMEM);
    cudaFuncSetAttribute(flash_attn,
                         cudaFuncAttributeMaxDynamicSharedMemorySize, FSMEM);

    split4<<<(MROWS * CDIM / 4 + 255) / 256, 256>>>(x, xh, xl, MROWS * CDIM / 4);
    transpose_split<<<dim3(QKVN / 32, CDIM / 32), dim3(32, 8)>>>(Wqkv, wqh, wql, QKVN);
    transpose_split<<<dim3(CDIM / 32, CDIM / 32), dim3(32, 8)>>>(Wproj, wph, wpl, CDIM);

    gemm_bf16s<1><<<dim3(QKVN / GBN, MROWS / GBM), 256, GSMEM>>>(
        xh, xl, wqh, wql, bqkv, nullptr, qkvh, qkvl, QKVN);

    flash_attn<<<dim3(SEQ / FBQ, NHEAD, BATCH), 256, FSMEM>>>(
        qkvh, qkvl, mask, yh, yl);

    gemm_bf16s<0><<<dim3(CDIM / GBN, MROWS / GBM), 256, GSMEM>>>(
        yh, yl, wph, wpl, bproj, out, nullptr, nullptr, CDIM);
}

// round 11
// speedup vs baseline: 3.1182x; 1.0740x over previous
#include <cuda_runtime.h>
#include <cuda_bf16.h>
#include <cstdint>

// ---------------------------------------------------------------------------
// Problem constants
// ---------------------------------------------------------------------------
#define BATCH 2
#define SEQ   2048
#define CDIM  1024
#define NHEAD 16
#define HDIM  64
#define MROWS (BATCH * SEQ)     // 4096
#define QKVN  (3 * CDIM)        // 3072

// GEMM tiling: 128x128 CTA tile, BK=32, XOR-swizzled 64B rows, 3-stage cp.async
#define GBM 128
#define GBN 128
#define GBK 32
#define G2TILE  (128 * 64)             // 8192 B (no padding; XOR swizzle)
#define G2STAGE (4 * G2TILE)           // 32768 B (Ah,Al,Bh,Bl)
#define G2SMEM  (3 * G2STAGE)          // 98304 B, 3 stages
#define NKT    (CDIM / GBK)            // 32

// Flash tiling (unchanged from R8/R9): 128 q-rows, 8 warps x 16 rows
#define FBQ    128
#define FPITCH 144
#define FQH 0
#define FQL (128 * FPITCH)
#define FKH (2 * 128 * FPITCH)
#define FKL (FKH + 64 * FPITCH)
#define FVH (FKL + 64 * FPITCH)
#define FVL (FVH + 64 * FPITCH)
#define FMASK (FVL + 64 * FPITCH)
#define FSMEM (FMASK + 64 * 4)         // 73984 B

// ---------------------------------------------------------------------------
// Scratch (allocation-free __device__ globals)
// ---------------------------------------------------------------------------
__device__ __align__(16) __nv_bfloat16 g_qkvh[MROWS * QKVN];
__device__ __align__(16) __nv_bfloat16 g_qkvl[MROWS * QKVN];
__device__ __align__(16) __nv_bfloat16 g_xh[MROWS * CDIM];
__device__ __align__(16) __nv_bfloat16 g_xl[MROWS * CDIM];
__device__ __align__(16) __nv_bfloat16 g_yh[MROWS * CDIM];
__device__ __align__(16) __nv_bfloat16 g_yl[MROWS * CDIM];
__device__ __align__(16) __nv_bfloat16 g_wqh[QKVN * CDIM];    // W^T [3072][1024]
__device__ __align__(16) __nv_bfloat16 g_wql[QKVN * CDIM];
__device__ __align__(16) __nv_bfloat16 g_wph[CDIM * CDIM];    // W^T [1024][1024]
__device__ __align__(16) __nv_bfloat16 g_wpl[CDIM * CDIM];

// ---------------------------------------------------------------------------
// PTX helpers (sm_80-era: valid on compute_103)
// ---------------------------------------------------------------------------
__device__ __forceinline__ uint32_t smem_u32(const void* p) {
    uint32_t a;
    asm("{ .reg .u64 t; cvta.to.shared.u64 t, %1; cvt.u32.u64 %0, t; }"
        : "=r"(a) : "l"(p));
    return a;
}
__device__ __forceinline__ void cp_async16(uint32_t dst, const void* src) {
    asm volatile("cp.async.cg.shared.global [%0], [%1], 16;"
                 :: "r"(dst), "l"(src) : "memory");
}
__device__ __forceinline__ void cp_commit() {
    asm volatile("cp.async.commit_group;" ::: "memory");
}
__device__ __forceinline__ void cp_wait1() {
    asm volatile("cp.async.wait_group 1;" ::: "memory");
}
__device__ __forceinline__ void cp_wait0() {
    asm volatile("cp.async.wait_group 0;" ::: "memory");
}
__device__ __forceinline__ void ldm4(uint32_t* r, uint32_t addr) {
    asm volatile("ldmatrix.sync.aligned.m8n8.x4.shared.b16 {%0,%1,%2,%3}, [%4];"
                 : "=r"(r[0]), "=r"(r[1]), "=r"(r[2]), "=r"(r[3]) : "r"(addr));
}
__device__ __forceinline__ void ldm4t(uint32_t* r, uint32_t addr) {
    asm volatile("ldmatrix.sync.aligned.m8n8.x4.trans.shared.b16 {%0,%1,%2,%3}, [%4];"
                 : "=r"(r[0]), "=r"(r[1]), "=r"(r[2]), "=r"(r[3]) : "r"(addr));
}
__device__ __forceinline__ void mma_bf16(float* c, const uint32_t* a,
                                         uint32_t b0, uint32_t b1) {
    asm volatile(
        "mma.sync.aligned.m16n8k16.row.col.f32.bf16.bf16.f32 "
        "{%0,%1,%2,%3}, {%4,%5,%6,%7}, {%8,%9}, {%0,%1,%2,%3};"
        : "+f"(c[0]), "+f"(c[1]), "+f"(c[2]), "+f"(c[3])
        : "r"(a[0]), "r"(a[1]), "r"(a[2]), "r"(a[3]), "r"(b0), "r"(b1));
}

// ---------------------------------------------------------------------------
// fp32 -> bf16 split helpers / conversion kernels
// ---------------------------------------------------------------------------
__device__ __forceinline__ void split_bf16(float a, __nv_bfloat16& h, __nv_bfloat16& l) {
    h = __float2bfloat16(a);
    l = __float2bfloat16(a - __bfloat162float(h));
}
__device__ __forceinline__ void split_pack2(float x, float y, uint32_t& hi, uint32_t& lo) {
    __nv_bfloat16 hx, lx, hy, ly;
    split_bf16(x, hx, lx);
    split_bf16(y, hy, ly);
    __nv_bfloat162 h2 = __halves2bfloat162(hx, hy);
    __nv_bfloat162 l2 = __halves2bfloat162(lx, ly);
    hi = *reinterpret_cast<uint32_t*>(&h2);
    lo = *reinterpret_cast<uint32_t*>(&l2);
}

__global__ __launch_bounds__(256)
void split4(const float* __restrict__ in, __nv_bfloat16* __restrict__ hi,
            __nv_bfloat16* __restrict__ lo, int n4)
{
    int i = blockIdx.x * blockDim.x + threadIdx.x;
    if (i >= n4) return;
    float4 v = reinterpret_cast<const float4*>(in)[i];
    uint32_t h0, l0, h1, l1;
    split_pack2(v.x, v.y, h0, l0);
    split_pack2(v.z, v.w, h1, l1);
    reinterpret_cast<uint32_t*>(hi)[2 * i]     = h0;
    reinterpret_cast<uint32_t*>(hi)[2 * i + 1] = h1;
    reinterpret_cast<uint32_t*>(lo)[2 * i]     = l0;
    reinterpret_cast<uint32_t*>(lo)[2 * i + 1] = l1;
}

// Transpose + split: W[1024][Ncols] fp32 -> T_hi/lo [Ncols][1024] bf16
__global__ __launch_bounds__(256)
void transpose_split(const float* __restrict__ W, __nv_bfloat16* __restrict__ Th,
                     __nv_bfloat16* __restrict__ Tl, int Ncols)
{
    __shared__ float t[32][33];
    const int tx = threadIdx.x, ty = threadIdx.y;
    const int n = blockIdx.x * 32 + tx;
    const int k0 = blockIdx.y * 32;
    #pragma unroll
    for (int j = 0; j < 4; j++)
        t[ty + j * 8][tx] = W[(size_t)(k0 + ty + j * 8) * Ncols + n];
    __syncthreads();
    const int nr = blockIdx.x * 32;
    #pragma unroll
    for (int j = 0; j < 4; j++) {
        float a = t[tx][ty + j * 8];
        __nv_bfloat16 h, l;
        split_bf16(a, h, l);
        size_t o = (size_t)(nr + ty + j * 8) * CDIM + k0 + tx;
        Th[o] = h; Tl[o] = l;
    }
}

// ---------------------------------------------------------------------------
// bf16 split GEMM via mma.sync: C = (Ah+Al) @ (Bh+Bl)^T + bias
// 3-stage cp.async pipeline, ONE barrier per k-tile, XOR-swizzled 64B rows:
// 16B chunk c of row r stored at c ^ ((r>>1)&3)  (conflict-free for ldmatrix
// phases and cp.async stores).
// ---------------------------------------------------------------------------
template<int SPLIT>
__global__ __launch_bounds__(256, 2)
void gemm_bf16s(const __nv_bfloat16* __restrict__ Ah, const __nv_bfloat16* __restrict__ Al,
                const __nv_bfloat16* __restrict__ Bh, const __nv_bfloat16* __restrict__ Bl,
                const float* __restrict__ bias, float* __restrict__ C,
                __nv_bfloat16* __restrict__ Ch, __nv_bfloat16* __restrict__ Cl, int N)
{
    extern __shared__ char sm[];
    const uint32_t sb = smem_u32(sm);
    const int tid = threadIdx.x;
    const int lane = tid & 31, warp = tid >> 5;
    const int wm = (warp >> 2) * 64;
    const int wn = (warp & 3) * 32;
    const int m0 = blockIdx.y * GBM, n0 = blockIdx.x * GBN;

    // Per-lane fragment addressing (swizzle XOR values are lane constants)
    const uint32_t arow = (uint32_t)(wm + (lane & 15)) * 64;
    const uint32_t asw  = (uint32_t)(((lane & 15) >> 1) & 3);
    const uint32_t ahi  = (uint32_t)(lane >> 4);           // A chunk parity
    const uint32_t brow = (uint32_t)(wn + (lane & 7) + ((lane >> 4) * 8)) * 64;
    const uint32_t bsw  = (uint32_t)(((lane & 7) >> 1) & 3);
    const uint32_t bhi  = (uint32_t)((lane >> 3) & 1);     // B chunk parity

    float acc[4][4][4];
    #pragma unroll
    for (int i = 0; i < 4; i++)
        #pragma unroll
        for (int j = 0; j < 4; j++)
            #pragma unroll
            for (int q = 0; q < 4; q++) acc[i][j][q] = 0.0f;

    auto issue = [&](int kt, int buf) {
        const int k0 = kt * GBK;
        const uint32_t stg = sb + buf * G2STAGE;
        #pragma unroll
        for (int l = 0; l < 8; l++) {
            const int t = l >> 1;
            const int idx = tid + (l & 1) * 256;
            const int r = idx >> 2, c = idx & 3;
            const __nv_bfloat16* base = (t == 0) ? Ah : (t == 1) ? Al
                                        : (t == 2) ? Bh : Bl;
            const int grow = ((t < 2) ? m0 : n0) + r;
            const uint32_t csw = (uint32_t)(c ^ ((r >> 1) & 3));
            cp_async16(stg + t * G2TILE + r * 64 + csw * 16,
                       base + (size_t)grow * CDIM + k0 + c * 8);
        }
        cp_commit();
    };

    issue(0, 0);
    issue(1, 1);
    for (int kt = 0; kt < NKT; kt++) {
        if (kt + 1 < NKT) cp_wait1();   // oldest group (kt) retired
        else              cp_wait0();
        __syncthreads();                // single barrier per k-tile
        if (kt + 2 < NKT) issue(kt + 2, (kt + 2) % 3);

        const uint32_t stg = sb + (kt % 3) * G2STAGE;
        const uint32_t t_ah = stg + 0 * G2TILE;
        const uint32_t t_al = stg + 1 * G2TILE;
        const uint32_t t_bh = stg + 2 * G2TILE;
        const uint32_t t_bl = stg + 3 * G2TILE;

        #pragma unroll
        for (int ks = 0; ks < 2; ks++) {
            const uint32_t ca = (uint32_t)(2 * ks) + ahi;   // A chunk index
            const uint32_t cb = (uint32_t)(2 * ks) + bhi;   // B chunk index
            uint32_t ah[4][4], al[4][4];
            #pragma unroll
            for (int mt = 0; mt < 4; mt++) {
                const uint32_t ao = arow + mt * (16 * 64) + ((ca ^ asw) << 4);
                ldm4(ah[mt], t_ah + ao);
                ldm4(al[mt], t_al + ao);
            }
            #pragma unroll
            for (int p = 0; p < 2; p++) {
                const uint32_t bo = brow + p * (16 * 64) + ((cb ^ bsw) << 4);
                uint32_t bh[4], bl[4];
                ldm4(bh, t_bh + bo);
                ldm4(bl, t_bl + bo);
                #pragma unroll
                for (int mt = 0; mt < 4; mt++)
                    #pragma unroll
                    for (int q = 0; q < 2; q++)
                        mma_bf16(acc[mt][2 * p + q], ah[mt], bh[2 * q], bh[2 * q + 1]);
                #pragma unroll
                for (int mt = 0; mt < 4; mt++)
                    #pragma unroll
                    for (int q = 0; q < 2; q++)
                        mma_bf16(acc[mt][2 * p + q], ah[mt], bl[2 * q], bl[2 * q + 1]);
                #pragma unroll
                for (int mt = 0; mt < 4; mt++)
                    #pragma unroll
                    for (int q = 0; q < 2; q++)
                        mma_bf16(acc[mt][2 * p + q], al[mt], bh[2 * q], bh[2 * q + 1]);
            }
        }
    }
    __syncthreads();

    const int erow = lane >> 2, ecol = (lane & 3) * 2;
    #pragma unroll
    for (int mt = 0; mt < 4; mt++) {
        #pragma unroll
        for (int nt = 0; nt < 4; nt++) {
            const int row = m0 + wm + mt * 16 + erow;
            const int col = n0 + wn + nt * 8 + ecol;
            const float2 bv = *reinterpret_cast<const float2*>(bias + col);
            const float v0x = acc[mt][nt][0] + bv.x;
            const float v0y = acc[mt][nt][1] + bv.y;
            const float v1x = acc[mt][nt][2] + bv.x;
            const float v1y = acc[mt][nt][3] + bv.y;
            if (SPLIT) {
                uint32_t hi, lo;
                split_pack2(v0x, v0y, hi, lo);
                *reinterpret_cast<uint32_t*>(Ch + (size_t)row * N + col) = hi;
                *reinterpret_cast<uint32_t*>(Cl + (size_t)row * N + col) = lo;
                split_pack2(v1x, v1y, hi, lo);
                *reinterpret_cast<uint32_t*>(Ch + (size_t)(row + 8) * N + col) = hi;
                *reinterpret_cast<uint32_t*>(Cl + (size_t)(row + 8) * N + col) = lo;
            } else {
                float2 v0; v0.x = v0x; v0.y = v0y;
                float2 v1; v1.x = v1x; v1.y = v1y;
                *reinterpret_cast<float2*>(C + (size_t)row * N + col) = v0;
                *reinterpret_cast<float2*>(C + (size_t)(row + 8) * N + col) = v1;
            }
        }
    }
}

// ---------------------------------------------------------------------------
// Flash attention via mma.sync (bf16 split, FA2 register-resident P).
// Unchanged from R9.
// ---------------------------------------------------------------------------
__global__ __launch_bounds__(256, 2)
void flash_attn(const __nv_bfloat16* __restrict__ qkvh,
                const __nv_bfloat16* __restrict__ qkvl,
                const int* __restrict__ mask,
                __nv_bfloat16* __restrict__ yh, __nv_bfloat16* __restrict__ yl)
{
    extern __shared__ char smp[];
    const uint32_t sb = smem_u32(smp);
    const int qt = blockIdx.x, h = blockIdx.y, b = blockIdx.z;
    const int tid = threadIdx.x, lane = tid & 31, warp = tid >> 5;
    const int wm = warp * 16;
    const int q0 = qt * FBQ;
    const int seqbase = b * SEQ;

    #pragma unroll
    for (int it = 0; it < 8; it++) {
        const int idx = tid + it * 256;
        const int r = idx >> 4, cc = idx & 15;
        const size_t go = (size_t)(seqbase + q0 + r) * QKVN + h * HDIM + cc * 4;
        *reinterpret_cast<uint2*>(smp + FQH + r * FPITCH + cc * 8) =
            *reinterpret_cast<const uint2*>(qkvh + go);
        *reinterpret_cast<uint2*>(smp + FQL + r * FPITCH + cc * 8) =
            *reinterpret_cast<const uint2*>(qkvl + go);
    }

    float oacc[8][4];
    #pragma unroll
    for (int nt = 0; nt < 8; nt++)
        #pragma unroll
        for (int q = 0; q < 4; q++) oacc[nt][q] = 0.0f;
    float m0 = -1e30f, m1 = -1e30f, l0 = 0.0f, l1 = 0.0f;
    const int rq0 = q0 + wm + (lane >> 2);
    const int rq1 = rq0 + 8;

    const uint32_t qhoff = sb + FQH + (wm + (lane & 15)) * FPITCH + (lane >> 4) * 16;
    const uint32_t qloff = sb + FQL + (wm + (lane & 15)) * FPITCH + (lane >> 4) * 16;
    const uint32_t kfrag = (uint32_t)(((lane & 7) + (lane >> 4) * 8) * FPITCH
                                      + ((lane >> 3) & 1) * 16);
    const uint32_t vfrag = (uint32_t)(((lane & 7) + ((lane >> 3) & 1) * 8) * FPITCH
                                      + (lane >> 4) * 16);

    const int nkt = 2 * qt + 2;
    for (int kt = 0; kt < nkt; kt++) {
        const int k0 = kt * 64;

        #pragma unroll
        for (int it = 0; it < 4; it++) {
            const int idx = tid + it * 256;
            const int r = idx >> 4, cc = idx & 15;
            const size_t gk = (size_t)(seqbase + k0 + r) * QKVN + CDIM + h * HDIM + cc * 4;
            *reinterpret_cast<uint2*>(smp + FKH + r * FPITCH + cc * 8) =
                *reinterpret_cast<const uint2*>(qkvh + gk);
            *reinterpret_cast<uint2*>(smp + FKL + r * FPITCH + cc * 8) =
                *reinterpret_cast<const uint2*>(qkvl + gk);
            *reinterpret_cast<uint2*>(smp + FVH + r * FPITCH + cc * 8) =
                *reinterpret_cast<const uint2*>(qkvh + gk + CDIM);
            *reinterpret_cast<uint2*>(smp + FVL + r * FPITCH + cc * 8) =
                *reinterpret_cast<const uint2*>(qkvl + gk + CDIM);
        }
        if (tid < 64)
            reinterpret_cast<float*>(smp + FMASK)[tid] =
                (__ldg(&mask[seqbase + k0 + tid]) != 0) ? 0.0f : -2e30f;
        __syncthreads();

        if (k0 <= q0 + wm + 15) {
            float sacc[8][4];
            #pragma unroll
            for (int nt = 0; nt < 8; nt++)
                #pragma unroll
                for (int q = 0; q < 4; q++) sacc[nt][q] = 0.0f;

            #pragma unroll
            for (int ks = 0; ks < 4; ks++) {
                uint32_t qhf[4], qlf[4];
                ldm4(qhf, qhoff + ks * 32);
                ldm4(qlf, qloff + ks * 32);
                #pragma unroll
                for (int gg = 0; gg < 2; gg++) {
                    uint32_t khf[2][4], klf[2][4];
                    #pragma unroll
                    for (int g2 = 0; g2 < 2; g2++) {
                        const uint32_t ka = (2 * gg + g2) * (16 * FPITCH) + kfrag + ks * 32;
                        ldm4(khf[g2], sb + FKH + ka);
                        ldm4(klf[g2], sb + FKL + ka);
                    }
                    #pragma unroll
                    for (int g2 = 0; g2 < 2; g2++)
                        #pragma unroll
                        for (int q = 0; q < 2; q++)
                            mma_bf16(sacc[2 * (2 * gg + g2) + q], qhf,
                                     khf[g2][2 * q], khf[g2][2 * q + 1]);
                    #pragma unroll
                    for (int g2 = 0; g2 < 2; g2++)
                        #pragma unroll
                        for (int q = 0; q < 2; q++)
                            mma_bf16(sacc[2 * (2 * gg + g2) + q], qhf,
                                     klf[g2][2 * q], klf[g2][2 * q + 1]);
                    #pragma unroll
                    for (int g2 = 0; g2 < 2; g2++)
                        #pragma unroll
                        for (int q = 0; q < 2; q++)
                            mma_bf16(sacc[2 * (2 * gg + g2) + q], qlf,
                                     khf[g2][2 * q], khf[g2][2 * q + 1]);
                }
            }

            const float* madd = reinterpret_cast<const float*>(smp + FMASK);
            float mx0 = -1e30f, mx1 = -1e30f;
            #pragma unroll
            for (int nt = 0; nt < 8; nt++) {
                const int kc = nt * 8 + (lane & 3) * 2;
                const int gk0 = k0 + kc, gk1 = gk0 + 1;
                const float a0 = madd[kc], a1 = madd[kc + 1];
                const float s0 = (gk0 <= rq0) ? sacc[nt][0] * 0.125f + a0 : -1e30f;
                const float s1 = (gk1 <= rq0) ? sacc[nt][1] * 0.125f + a1 : -1e30f;
                const float s2 = (gk0 <= rq1) ? sacc[nt][2] * 0.125f + a0 : -1e30f;
                const float s3 = (gk1 <= rq1) ? sacc[nt][3] * 0.125f + a1 : -1e30f;
                sacc[nt][0] = s0; sacc[nt][1] = s1; sacc[nt][2] = s2; sacc[nt][3] = s3;
                mx0 = fmaxf(mx0, fmaxf(s0, s1));
                mx1 = fmaxf(mx1, fmaxf(s2, s3));
            }
            mx0 = fmaxf(mx0, __shfl_xor_sync(0xffffffffu, mx0, 1));
            mx0 = fmaxf(mx0, __shfl_xor_sync(0xffffffffu, mx0, 2));
            mx1 = fmaxf(mx1, __shfl_xor_sync(0xffffffffu, mx1, 1));
            mx1 = fmaxf(mx1, __shfl_xor_sync(0xffffffffu, mx1, 2));
            const float mn0 = fmaxf(fmaxf(m0, mx0), -1e29f);
            const float mn1 = fmaxf(fmaxf(m1, mx1), -1e29f);
            const float al0 = __expf(m0 - mn0), al1 = __expf(m1 - mn1);
            m0 = mn0; m1 = mn1;
            float sum0 = 0.0f, sum1 = 0.0f;
            #pragma unroll
            for (int nt = 0; nt < 8; nt++) {
                float p;
                p = __expf(sacc[nt][0] - mn0); sacc[nt][0] = p; sum0 += p;
                p = __expf(sacc[nt][1] - mn0); sacc[nt][1] = p; sum0 += p;
                p = __expf(sacc[nt][2] - mn1); sacc[nt][2] = p; sum1 += p;
                p = __expf(sacc[nt][3] - mn1); sacc[nt][3] = p; sum1 += p;
            }
            sum0 += __shfl_xor_sync(0xffffffffu, sum0, 1);
            sum0 += __shfl_xor_sync(0xffffffffu, sum0, 2);
            sum1 += __shfl_xor_sync(0xffffffffu, sum1, 1);
            sum1 += __shfl_xor_sync(0xffffffffu, sum1, 2);
            l0 = l0 * al0 + sum0;
            l1 = l1 * al1 + sum1;
            #pragma unroll
            for (int nt = 0; nt < 8; nt++) {
                oacc[nt][0] *= al0; oacc[nt][1] *= al0;
                oacc[nt][2] *= al1; oacc[nt][3] *= al1;
            }

            #pragma unroll
            for (int ks = 0; ks < 4; ks++) {
                uint32_t pha[4], pla[4];
                split_pack2(sacc[2 * ks][0],     sacc[2 * ks][1],     pha[0], pla[0]);
                split_pack2(sacc[2 * ks][2],     sacc[2 * ks][3],     pha[1], pla[1]);
                split_pack2(sacc[2 * ks + 1][0], sacc[2 * ks + 1][1], pha[2], pla[2]);
                split_pack2(sacc[2 * ks + 1][2], sacc[2 * ks + 1][3], pha[3], pla[3]);
                #pragma unroll
                for (int gg = 0; gg < 2; gg++) {
                    uint32_t vhf[2][4], vlf[2][4];
                    #pragma unroll
                    for (int g2 = 0; g2 < 2; g2++) {
                        const uint32_t va = (ks * 16) * FPITCH + vfrag
                                            + (2 * gg + g2) * 32;
                        ldm4t(vhf[g2], sb + FVH + va);
                        ldm4t(vlf[g2], sb + FVL + va);
                    }
                    #pragma unroll
                    for (int g2 = 0; g2 < 2; g2++)
                        #pragma unroll
                        for (int q = 0; q < 2; q++)
                            mma_bf16(oacc[2 * (2 * gg + g2) + q], pha,
                                     vhf[g2][2 * q], vhf[g2][2 * q + 1]);
                    #pragma unroll
                    for (int g2 = 0; g2 < 2; g2++)
                        #pragma unroll
                        for (int q = 0; q < 2; q++)
                            mma_bf16(oacc[2 * (2 * gg + g2) + q], pha,
                                     vlf[g2][2 * q], vlf[g2][2 * q + 1]);
                    #pragma unroll
                    for (int g2 = 0; g2 < 2; g2++)
                        #pragma unroll
                        for (int q = 0; q < 2; q++)
                            mma_bf16(oacc[2 * (2 * gg + g2) + q], pla,
                                     vhf[g2][2 * q], vhf[g2][2 * q + 1]);
                }
            }
        }
        __syncthreads();
    }

    const float inv0 = 1.0f / l0, inv1 = 1.0f / l1;
    const int row0 = seqbase + q0 + wm + (lane >> 2);
    #pragma unroll
    for (int nt = 0; nt < 8; nt++) {
        const int col = h * HDIM + nt * 8 + (lane & 3) * 2;
        uint32_t hi, lo;
        split_pack2(oacc[nt][0] * inv0, oacc[nt][1] * inv0, hi, lo);
        *reinterpret_cast<uint32_t*>(yh + (size_t)row0 * CDIM + col) = hi;
        *reinterpret_cast<uint32_t*>(yl + (size_t)row0 * CDIM + col) = lo;
        split_pack2(oacc[nt][2] * inv1, oacc[nt][3] * inv1, hi, lo);
        *reinterpret_cast<uint32_t*>(yh + (size_t)(row0 + 8) * CDIM + col) = hi;
        *reinterpret_cast<uint32_t*>(yl + (size_t)(row0 + 8) * CDIM + col) = lo;
    }
}

// ---------------------------------------------------------------------------
// Launch
// ---------------------------------------------------------------------------
extern "C" void kernel_launch(void* const* d_in, const int* in_sizes, int n_in,
                              void* d_out, int out_size)
{
    const float* x     = (const float*)d_in[0];
    const int*   mask  = (const int*)  d_in[1];
    const float* Wqkv  = (const float*)d_in[2];
    const float* bqkv  = (const float*)d_in[3];
    const float* Wproj = (const float*)d_in[4];
    const float* bproj = (const float*)d_in[5];
    float* out = (float*)d_out;

    __nv_bfloat16 *qkvh, *qkvl, *xh, *xl, *yh, *yl, *wqh, *wql, *wph, *wpl;
    cudaGetSymbolAddress((void**)&qkvh, g_qkvh);
    cudaGetSymbolAddress((void**)&qkvl, g_qkvl);
    cudaGetSymbolAddress((void**)&xh, g_xh);
    cudaGetSymbolAddress((void**)&xl, g_xl);
    cudaGetSymbolAddress((void**)&yh, g_yh);
    cudaGetSymbolAddress((void**)&yl, g_yl);
    cudaGetSymbolAddress((void**)&wqh, g_wqh);
    cudaGetSymbolAddress((void**)&wql, g_wql);
    cudaGetSymbolAddress((void**)&wph, g_wph);
    cudaGetSymbolAddress((void**)&wpl, g_wpl);

    cudaFuncSetAttribute(gemm_bf16s<0>,
                         cudaFuncAttributeMaxDynamicSharedMemorySize, G2SMEM);
    cudaFuncSetAttribute(gemm_bf16s<1>,
                         cudaFuncAttributeMaxDynamicSharedMemorySize, G2SMEM);
    cudaFuncSetAttribute(flash_attn,
                         cudaFuncAttributeMaxDynamicSharedMemorySize, FSMEM);

    split4<<<(MROWS * CDIM / 4 + 255) / 256, 256>>>(x, xh, xl, MROWS * CDIM / 4);
    transpose_split<<<dim3(QKVN / 32, CDIM / 32), dim3(32, 8)>>>(Wqkv, wqh, wql, QKVN);
    transpose_split<<<dim3(CDIM / 32, CDIM / 32), dim3(32, 8)>>>(Wproj, wph, wpl, CDIM);

    gemm_bf16s<1><<<dim3(QKVN / GBN, MROWS / GBM), 256, G2SMEM>>>(
        xh, xl, wqh, wql, bqkv, nullptr, qkvh, qkvl, QKVN);

    flash_attn<<<dim3(SEQ / FBQ, NHEAD, BATCH), 256, FSMEM>>>(
        qkvh, qkvl, mask, yh, yl);

    gemm_bf16s<0><<<dim3(CDIM / GBN, MROWS / GBM), 256, G2SMEM>>>(
        yh, yl, wph, wpl, bproj, out, nullptr, nullptr, CDIM);
}